// round 2
// baseline (speedup 1.0000x reference)
#include <cuda_runtime.h>
#include <cuda_bf16.h>
#include <cstdint>

#define NN 4096
#define DQ 128
#define UW 160          // padded U width (128 v-cols + 1 denom col + pad)
#define SPLITK 4

// ---------------- scratch (static device globals; no allocation) ----------------
__device__ __nv_bfloat16 d_G [(size_t)NN * NN];         // 32 MB: hi plane of exp(trans^T)
__device__ __nv_bfloat16 d_Gl[(size_t)NN * NN];         // 32 MB: lo plane (residual)
__device__ float         d_h [(size_t)NN * DQ];         // 2 MB : current node features
__device__ __nv_bfloat16 d_U [(size_t)NN * UW];         // hi plane: e^{sa}*v | e^{sa} | 0
__device__ __nv_bfloat16 d_Ul[(size_t)NN * UW];         // lo plane
__device__ float         d_part[(size_t)SPLITK * NN * UW]; // split-K partials

// ---------------- PTX helpers ----------------
__device__ __forceinline__ uint32_t smem_u32(const void* p) {
    return (uint32_t)__cvta_generic_to_shared(p);
}
__device__ __forceinline__ void ldsm_x4(uint32_t& r0, uint32_t& r1, uint32_t& r2, uint32_t& r3, uint32_t a) {
    asm volatile("ldmatrix.sync.aligned.m8n8.x4.shared.b16 {%0,%1,%2,%3},[%4];"
                 : "=r"(r0), "=r"(r1), "=r"(r2), "=r"(r3) : "r"(a));
}
__device__ __forceinline__ void ldsm_x4t(uint32_t& r0, uint32_t& r1, uint32_t& r2, uint32_t& r3, uint32_t a) {
    asm volatile("ldmatrix.sync.aligned.m8n8.x4.trans.shared.b16 {%0,%1,%2,%3},[%4];"
                 : "=r"(r0), "=r"(r1), "=r"(r2), "=r"(r3) : "r"(a));
}
__device__ __forceinline__ void mma_bf16(float& d0, float& d1, float& d2, float& d3,
                                         uint32_t a0, uint32_t a1, uint32_t a2, uint32_t a3,
                                         uint32_t b0, uint32_t b1) {
    asm volatile(
        "mma.sync.aligned.m16n8k16.row.col.f32.bf16.bf16.f32 "
        "{%0,%1,%2,%3},{%4,%5,%6,%7},{%8,%9},{%0,%1,%2,%3};"
        : "+f"(d0), "+f"(d1), "+f"(d2), "+f"(d3)
        : "r"(a0), "r"(a1), "r"(a2), "r"(a3), "r"(b0), "r"(b1));
}
__device__ __forceinline__ void split_bf16(float x, __nv_bfloat16& hi, __nv_bfloat16& lo) {
    hi = __float2bfloat16(x);
    lo = __float2bfloat16(x - __bfloat162float(hi));
}

// ---------------- 1. encode: h = [x|comms] @ W_enc + b_enc ----------------
__global__ __launch_bounds__(128) void encode_kernel(
    const float* __restrict__ x, const float* __restrict__ comms,
    const float* __restrict__ W_enc, const float* __restrict__ b_enc)
{
    const int i0 = blockIdx.x * 16;
    const int c = threadIdx.x;
    __shared__ float in[16][96];
    for (int idx = c; idx < 16 * 64; idx += 128) {
        int r = idx >> 6, t = idx & 63;
        in[r][t] = x[(size_t)(i0 + r) * 64 + t];
    }
    for (int idx = c; idx < 16 * 32; idx += 128) {
        int r = idx >> 5, t = idx & 31;
        in[r][64 + t] = comms[(size_t)(i0 + r) * 32 + t];
    }
    __syncthreads();
    float acc[16];
    const float be = b_enc[c];
#pragma unroll
    for (int r = 0; r < 16; r++) acc[r] = be;
#pragma unroll 4
    for (int t = 0; t < 96; t++) {
        float w = W_enc[t * DQ + c];
#pragma unroll
        for (int r = 0; r < 16; r++) acc[r] += in[r][t] * w;
    }
#pragma unroll
    for (int r = 0; r < 16; r++) d_h[(size_t)(i0 + r) * DQ + c] = acc[r];
}

// ---------------- 2. build G planes: G[i][j] = exp(trans[j][i]), split-bf16 ----------------
__global__ __launch_bounds__(256) void buildG_kernel(const float* __restrict__ trans)
{
    __shared__ float t[32][33];
    const int i0 = blockIdx.x * 32, j0 = blockIdx.y * 32;
    const int tx = threadIdx.x, ty = threadIdx.y; // (32, 8)
#pragma unroll
    for (int r = 0; r < 4; r++)
        t[ty + 8 * r][tx] = trans[(size_t)(j0 + ty + 8 * r) * NN + i0 + tx];
    __syncthreads();
#pragma unroll
    for (int r = 0; r < 4; r++) {
        float v = t[tx][ty + 8 * r];
        float e = (v == 0.f) ? 0.f : __expf(v);   // tb==0 -> -inf -> weight 0
        __nv_bfloat16 hi, lo;
        split_bf16(e, hi, lo);
        size_t idx = (size_t)(i0 + ty + 8 * r) * NN + j0 + tx;
        d_G[idx] = hi;
        d_Gl[idx] = lo;
    }
}

// ---------------- 3. per-layer U planes ----------------
// U[j][c<128] = exp(sa_j)*v[j][c]; U[j][128] = exp(sa_j); U[j][129..159] = 0
__global__ __launch_bounds__(128) void computeU_kernel(
    const float* __restrict__ W_ad, const float* __restrict__ b_ad,
    const float* __restrict__ wa,   const float* __restrict__ W_av,
    const float* __restrict__ b_av)
{
    const int j0 = blockIdx.x * 16;
    const int c = threadIdx.x;
    __shared__ float hr[16][DQ];
    __shared__ float prod[16][DQ + 1];
    __shared__ float es_s[16];
#pragma unroll
    for (int r = 0; r < 16; r++) hr[r][c] = d_h[(size_t)(j0 + r) * DQ + c];
    __syncthreads();

    float acc[16];
    const float bad = b_ad[c];
#pragma unroll
    for (int r = 0; r < 16; r++) acc[r] = bad;
#pragma unroll 4
    for (int t = 0; t < DQ; t++) {
        float w = W_ad[t * DQ + c];
#pragma unroll
        for (int r = 0; r < 16; r++) acc[r] += hr[r][t] * w;
    }
    const float wac = wa[c];
#pragma unroll
    for (int r = 0; r < 16; r++) prod[r][c] = acc[r] * wac;
    __syncthreads();

    const int warp = c >> 5, lane = c & 31;
#pragma unroll
    for (int rr = 0; rr < 4; rr++) {
        int r = warp * 4 + rr;
        float s = prod[r][lane] + prod[r][lane + 32] + prod[r][lane + 64] + prod[r][lane + 96];
#pragma unroll
        for (int o = 16; o > 0; o >>= 1) s += __shfl_xor_sync(0xffffffff, s, o);
        if (lane == 0) es_s[r] = __expf(s);
    }
    __syncthreads();

    const float bav = b_av[c];
#pragma unroll
    for (int r = 0; r < 16; r++) acc[r] = bav;
#pragma unroll 4
    for (int t = 0; t < DQ; t++) {
        float w = W_av[t * DQ + c];
#pragma unroll
        for (int r = 0; r < 16; r++) acc[r] += hr[r][t] * w;
    }
#pragma unroll
    for (int r = 0; r < 16; r++) {
        __nv_bfloat16 hi, lo;
        split_bf16(es_s[r] * acc[r], hi, lo);
        size_t idx = (size_t)(j0 + r) * UW + c;
        d_U[idx] = hi;
        d_Ul[idx] = lo;
    }
    if (c < 32) {
#pragma unroll
        for (int r = 0; r < 16; r++) {
            __nv_bfloat16 hi = __float2bfloat16(0.f), lo = __float2bfloat16(0.f);
            if (c == 0) split_bf16(es_s[r], hi, lo);
            size_t idx = (size_t)(j0 + r) * UW + 128 + c;
            d_U[idx] = hi;
            d_Ul[idx] = lo;
        }
    }
}

// ---------------- 4. split-K split-bf16 GEMM ----------------
// acc = Ghi*Uhi + Ghi*Ulo + Glo*Uhi  (lo*lo dropped; ~1.5e-5 rel)
// BM=64, BN=160, BK=32. Grid (64 M-tiles, SPLITK). 256 threads, warps 4(M)x2(N).
// Dynamic smem: A planes [2buf][2pl][64][40], B planes [2buf][2pl][32][168].
#define A_PB 2560      // 64*40 elems per (buf,plane)
#define B_PB 5376      // 32*168
#define ASOFF(buf, pl) (((buf) * 2 + (pl)) * A_PB)
#define BSOFF(buf, pl) (4 * A_PB + ((buf) * 2 + (pl)) * B_PB)
#define GEMM_SMEM_BYTES ((4 * A_PB + 4 * B_PB) * 2)

__global__ __launch_bounds__(256, 2) void gemm_kernel()
{
    extern __shared__ __nv_bfloat16 sm[];
    const int tid = threadIdx.x;
    const int m0 = blockIdx.x * 64;
    const size_t ks = (size_t)blockIdx.y * (NN / SPLITK);
    const int warp = tid >> 5, lane = tid & 31;
    const int wm = (warp & 3) * 16, wn = (warp >> 2) * 80;

    float acc[10][4];
#pragma unroll
    for (int i = 0; i < 10; i++)
        acc[i][0] = acc[i][1] = acc[i][2] = acc[i][3] = 0.f;

    const int arow = tid >> 2, aseg = tid & 3;
    const int br0 = tid / 20,         bs0 = tid % 20;
    const int br1 = (tid + 256) / 20, bs1 = (tid + 256) % 20;
    const int br2 = (tid + 512) / 20, bs2 = (tid + 512) % 20;
    const bool bok2 = tid < 128;  // 640 uint4 segments over 256 threads

    const size_t aoff = (size_t)(m0 + arow) * NN + ks + aseg * 8;
    const __nv_bfloat16* Agh = d_G + aoff;
    const __nv_bfloat16* Agl = d_Gl + aoff;
    const __nv_bfloat16* Ugh = d_U + ks * UW;
    const __nv_bfloat16* Ugl = d_Ul + ks * UW;

    uint4 aFh, aFl, bFh0, bFh1, bFh2, bFl0, bFl1, bFl2;
    // prologue: stage 0
    aFh = *(const uint4*)(Agh);
    aFl = *(const uint4*)(Agl);
    bFh0 = *(const uint4*)(Ugh + (size_t)br0 * UW + bs0 * 8);
    bFh1 = *(const uint4*)(Ugh + (size_t)br1 * UW + bs1 * 8);
    bFl0 = *(const uint4*)(Ugl + (size_t)br0 * UW + bs0 * 8);
    bFl1 = *(const uint4*)(Ugl + (size_t)br1 * UW + bs1 * 8);
    if (bok2) {
        bFh2 = *(const uint4*)(Ugh + (size_t)br2 * UW + bs2 * 8);
        bFl2 = *(const uint4*)(Ugl + (size_t)br2 * UW + bs2 * 8);
    }
    *(uint4*)&sm[ASOFF(0, 0) + arow * 40 + aseg * 8] = aFh;
    *(uint4*)&sm[ASOFF(0, 1) + arow * 40 + aseg * 8] = aFl;
    *(uint4*)&sm[BSOFF(0, 0) + br0 * 168 + bs0 * 8] = bFh0;
    *(uint4*)&sm[BSOFF(0, 0) + br1 * 168 + bs1 * 8] = bFh1;
    *(uint4*)&sm[BSOFF(0, 1) + br0 * 168 + bs0 * 8] = bFl0;
    *(uint4*)&sm[BSOFF(0, 1) + br1 * 168 + bs1 * 8] = bFl1;
    if (bok2) {
        *(uint4*)&sm[BSOFF(0, 0) + br2 * 168 + bs2 * 8] = bFh2;
        *(uint4*)&sm[BSOFF(0, 1) + br2 * 168 + bs2 * 8] = bFl2;
    }
    __syncthreads();

#pragma unroll 1
    for (int s = 0; s < 32; s++) {
        const int buf = s & 1;
        if (s + 1 < 32) {  // prefetch next tile to regs
            const size_t ko = (size_t)(s + 1) * 32;
            aFh = *(const uint4*)(Agh + ko);
            aFl = *(const uint4*)(Agl + ko);
            const __nv_bfloat16* U2h = Ugh + ko * UW;
            const __nv_bfloat16* U2l = Ugl + ko * UW;
            bFh0 = *(const uint4*)(U2h + (size_t)br0 * UW + bs0 * 8);
            bFh1 = *(const uint4*)(U2h + (size_t)br1 * UW + bs1 * 8);
            bFl0 = *(const uint4*)(U2l + (size_t)br0 * UW + bs0 * 8);
            bFl1 = *(const uint4*)(U2l + (size_t)br1 * UW + bs1 * 8);
            if (bok2) {
                bFh2 = *(const uint4*)(U2h + (size_t)br2 * UW + bs2 * 8);
                bFl2 = *(const uint4*)(U2l + (size_t)br2 * UW + bs2 * 8);
            }
        }
#pragma unroll
        for (int kk = 0; kk < 2; kk++) {
            uint32_t ah0, ah1, ah2, ah3, al0, al1, al2, al3;
            const int arw = wm + (lane & 15), acl = kk * 16 + (lane >> 4) * 8;
            ldsm_x4(ah0, ah1, ah2, ah3, smem_u32(&sm[ASOFF(buf, 0) + arw * 40 + acl]));
            ldsm_x4(al0, al1, al2, al3, smem_u32(&sm[ASOFF(buf, 1) + arw * 40 + acl]));
#pragma unroll
            for (int nf = 0; nf < 5; nf++) {
                uint32_t bh0, bh1, bh2, bh3, bl0, bl1, bl2, bl3;
                const int brw = kk * 16 + (lane & 15), bcl = wn + nf * 16 + (lane >> 4) * 8;
                ldsm_x4t(bh0, bh1, bh2, bh3, smem_u32(&sm[BSOFF(buf, 0) + brw * 168 + bcl]));
                ldsm_x4t(bl0, bl1, bl2, bl3, smem_u32(&sm[BSOFF(buf, 1) + brw * 168 + bcl]));
                float* c0 = acc[2 * nf];
                float* c1 = acc[2 * nf + 1];
                // hi*hi
                mma_bf16(c0[0], c0[1], c0[2], c0[3], ah0, ah1, ah2, ah3, bh0, bh1);
                mma_bf16(c1[0], c1[1], c1[2], c1[3], ah0, ah1, ah2, ah3, bh2, bh3);
                // hi*lo
                mma_bf16(c0[0], c0[1], c0[2], c0[3], ah0, ah1, ah2, ah3, bl0, bl1);
                mma_bf16(c1[0], c1[1], c1[2], c1[3], ah0, ah1, ah2, ah3, bl2, bl3);
                // lo*hi
                mma_bf16(c0[0], c0[1], c0[2], c0[3], al0, al1, al2, al3, bh0, bh1);
                mma_bf16(c1[0], c1[1], c1[2], c1[3], al0, al1, al2, al3, bh2, bh3);
            }
        }
        if (s + 1 < 32) {
            const int nb = (s + 1) & 1;
            *(uint4*)&sm[ASOFF(nb, 0) + arow * 40 + aseg * 8] = aFh;
            *(uint4*)&sm[ASOFF(nb, 1) + arow * 40 + aseg * 8] = aFl;
            *(uint4*)&sm[BSOFF(nb, 0) + br0 * 168 + bs0 * 8] = bFh0;
            *(uint4*)&sm[BSOFF(nb, 0) + br1 * 168 + bs1 * 8] = bFh1;
            *(uint4*)&sm[BSOFF(nb, 1) + br0 * 168 + bs0 * 8] = bFl0;
            *(uint4*)&sm[BSOFF(nb, 1) + br1 * 168 + bs1 * 8] = bFl1;
            if (bok2) {
                *(uint4*)&sm[BSOFF(nb, 0) + br2 * 168 + bs2 * 8] = bFh2;
                *(uint4*)&sm[BSOFF(nb, 1) + br2 * 168 + bs2 * 8] = bFl2;
            }
        }
        __syncthreads();
    }

    // epilogue: write split partials (no atomics -> deterministic)
    const int g = lane >> 2, tg = lane & 3;
    float* P = d_part + ((size_t)blockIdx.y * NN + m0 + wm) * UW + wn;
#pragma unroll
    for (int nf = 0; nf < 10; nf++) {
        int col = nf * 8 + tg * 2;
        *(float2*)&P[(size_t)g * UW + col] = make_float2(acc[nf][0], acc[nf][1]);
        *(float2*)&P[(size_t)(g + 8) * UW + col] = make_float2(acc[nf][2], acc[nf][3]);
    }
}

// ---------------- 5. reduce splits + softmax normalize: h = num / den ----------------
__global__ __launch_bounds__(128) void norm_kernel()
{
    const int i = blockIdx.x, c = threadIdx.x;
    const float* p = d_part + (size_t)i * UW;
    float num = 0.f, den = 0.f;
#pragma unroll
    for (int s = 0; s < SPLITK; s++) {
        num += p[(size_t)s * NN * UW + c];
        den += p[(size_t)s * NN * UW + 128];
    }
    d_h[(size_t)i * DQ + c] = num / den;
}

// ---------------- 6. decode: out = h @ W_dec + b_dec (+mask) ----------------
__global__ __launch_bounds__(128) void decode_kernel(
    const float* __restrict__ W_dec, const float* __restrict__ b_dec,
    const int* __restrict__ mask, float* __restrict__ out)
{
    const int i = blockIdx.x, c = threadIdx.x;
    __shared__ float red[128];
    red[c] = d_h[(size_t)i * DQ + c] * W_dec[c];
    __syncthreads();
    for (int off = 64; off > 0; off >>= 1) {
        if (c < off) red[c] += red[c + off];
        __syncthreads();
    }
    if (c == 0)
        out[i] = (mask[i] == 0) ? __int_as_float(0xff800000) : (red[0] + b_dec[0]);
}

// ---------------- launch ----------------
extern "C" void kernel_launch(void* const* d_in, const int* in_sizes, int n_in,
                              void* d_out, int out_size)
{
    const float* x      = (const float*)d_in[0];
    const float* comms  = (const float*)d_in[1];
    const float* trans  = (const float*)d_in[2];
    const int*   mask   = (const int*)d_in[3];
    const float* W_enc  = (const float*)d_in[4];
    const float* b_enc  = (const float*)d_in[5];
    const float* W_ad   = (const float*)d_in[6];
    const float* b_ad   = (const float*)d_in[7];
    const float* w_att  = (const float*)d_in[8];
    // d_in[9] = b_att: cancels in row-softmax, unused
    const float* W_av   = (const float*)d_in[10];
    const float* b_av   = (const float*)d_in[11];
    const float* W_dec  = (const float*)d_in[12];
    const float* b_dec  = (const float*)d_in[13];
    float* out = (float*)d_out;

    cudaFuncSetAttribute(gemm_kernel, cudaFuncAttributeMaxDynamicSharedMemorySize,
                         GEMM_SMEM_BYTES);

    encode_kernel<<<NN / 16, 128>>>(x, comms, W_enc, b_enc);
    buildG_kernel<<<dim3(NN / 32, NN / 32), dim3(32, 8)>>>(trans);

    for (int k = 0; k < 3; k++) {
        computeU_kernel<<<NN / 16, 128>>>(W_ad + (size_t)k * DQ * DQ,
                                          b_ad + (size_t)k * DQ,
                                          w_att + (size_t)k * 2 * DQ,   // wa = first half
                                          W_av + (size_t)k * DQ * DQ,
                                          b_av + (size_t)k * DQ);
        gemm_kernel<<<dim3(NN / 64, SPLITK), 256, GEMM_SMEM_BYTES>>>();
        norm_kernel<<<NN, 128>>>();
    }
    decode_kernel<<<NN, 128>>>(W_dec, b_dec, mask, out);
}

// round 3
// speedup vs baseline: 1.2893x; 1.2893x over previous
#include <cuda_runtime.h>
#include <cuda_fp16.h>
#include <cstdint>

#define NN 4096
#define DQ 128
#define UW 160          // padded U width (128 v-cols + 1 denom col + pad)
#define SPLITK 4

// ---------------- scratch (static device globals; no allocation) ----------------
__device__ __half d_G[(size_t)NN * NN];                 // 32 MB: exp(trans^T) fp16
__device__ float  d_h[(size_t)NN * DQ];                 // 2 MB : current node features
__device__ __half d_U[(size_t)NN * UW];                 // 1.25MB: e^{sa}*v | e^{sa} | 0
__device__ float  d_part[(size_t)SPLITK * NN * UW];     // split-K partials

// ---------------- PTX helpers ----------------
__device__ __forceinline__ uint32_t smem_u32(const void* p) {
    return (uint32_t)__cvta_generic_to_shared(p);
}
__device__ __forceinline__ void ldsm_x4(uint32_t& r0, uint32_t& r1, uint32_t& r2, uint32_t& r3, uint32_t a) {
    asm volatile("ldmatrix.sync.aligned.m8n8.x4.shared.b16 {%0,%1,%2,%3},[%4];"
                 : "=r"(r0), "=r"(r1), "=r"(r2), "=r"(r3) : "r"(a));
}
__device__ __forceinline__ void ldsm_x4t(uint32_t& r0, uint32_t& r1, uint32_t& r2, uint32_t& r3, uint32_t a) {
    asm volatile("ldmatrix.sync.aligned.m8n8.x4.trans.shared.b16 {%0,%1,%2,%3},[%4];"
                 : "=r"(r0), "=r"(r1), "=r"(r2), "=r"(r3) : "r"(a));
}
__device__ __forceinline__ void mma_f16(float& d0, float& d1, float& d2, float& d3,
                                        uint32_t a0, uint32_t a1, uint32_t a2, uint32_t a3,
                                        uint32_t b0, uint32_t b1) {
    asm volatile(
        "mma.sync.aligned.m16n8k16.row.col.f32.f16.f16.f32 "
        "{%0,%1,%2,%3},{%4,%5,%6,%7},{%8,%9},{%0,%1,%2,%3};"
        : "+f"(d0), "+f"(d1), "+f"(d2), "+f"(d3)
        : "r"(a0), "r"(a1), "r"(a2), "r"(a3), "r"(b0), "r"(b1));
}

// ---------------- 1. encode: h = [x|comms] @ W_enc + b_enc ----------------
__global__ __launch_bounds__(128) void encode_kernel(
    const float* __restrict__ x, const float* __restrict__ comms,
    const float* __restrict__ W_enc, const float* __restrict__ b_enc)
{
    const int i0 = blockIdx.x * 16;
    const int c = threadIdx.x;
    __shared__ float in[16][96];
    for (int idx = c; idx < 16 * 64; idx += 128) {
        int r = idx >> 6, t = idx & 63;
        in[r][t] = x[(size_t)(i0 + r) * 64 + t];
    }
    for (int idx = c; idx < 16 * 32; idx += 128) {
        int r = idx >> 5, t = idx & 31;
        in[r][64 + t] = comms[(size_t)(i0 + r) * 32 + t];
    }
    __syncthreads();
    float acc[16];
    const float be = b_enc[c];
#pragma unroll
    for (int r = 0; r < 16; r++) acc[r] = be;
#pragma unroll 4
    for (int t = 0; t < 96; t++) {
        float w = W_enc[t * DQ + c];
#pragma unroll
        for (int r = 0; r < 16; r++) acc[r] += in[r][t] * w;
    }
#pragma unroll
    for (int r = 0; r < 16; r++) d_h[(size_t)(i0 + r) * DQ + c] = acc[r];
}

// ---------------- 2. build G: G[i][j] = exp(trans[j][i]) in fp16 ----------------
__global__ __launch_bounds__(256) void buildG_kernel(const float* __restrict__ trans)
{
    __shared__ float t[32][33];
    const int i0 = blockIdx.x * 32, j0 = blockIdx.y * 32;
    const int tx = threadIdx.x, ty = threadIdx.y; // (32, 8)
#pragma unroll
    for (int r = 0; r < 4; r++)
        t[ty + 8 * r][tx] = trans[(size_t)(j0 + ty + 8 * r) * NN + i0 + tx];
    __syncthreads();
#pragma unroll
    for (int r = 0; r < 4; r++) {
        float v = t[tx][ty + 8 * r];
        float e = (v == 0.f) ? 0.f : __expf(v);   // tb==0 -> -inf -> weight 0
        d_G[(size_t)(i0 + ty + 8 * r) * NN + j0 + tx] = __float2half(e);
    }
}

// ---------------- 3. per-layer U (fp16) ----------------
// U[j][c<128] = exp(sa_j)*v[j][c]; U[j][128] = exp(sa_j); U[j][129..159] = 0
__global__ __launch_bounds__(128) void computeU_kernel(
    const float* __restrict__ W_ad, const float* __restrict__ b_ad,
    const float* __restrict__ wa,   const float* __restrict__ W_av,
    const float* __restrict__ b_av)
{
    const int j0 = blockIdx.x * 16;
    const int c = threadIdx.x;
    __shared__ float hr[16][DQ];
    __shared__ float prod[16][DQ + 1];
    __shared__ float es_s[16];
#pragma unroll
    for (int r = 0; r < 16; r++) hr[r][c] = d_h[(size_t)(j0 + r) * DQ + c];
    __syncthreads();

    float acc[16];
    const float bad = b_ad[c];
#pragma unroll
    for (int r = 0; r < 16; r++) acc[r] = bad;
#pragma unroll 4
    for (int t = 0; t < DQ; t++) {
        float w = W_ad[t * DQ + c];
#pragma unroll
        for (int r = 0; r < 16; r++) acc[r] += hr[r][t] * w;
    }
    const float wac = wa[c];
#pragma unroll
    for (int r = 0; r < 16; r++) prod[r][c] = acc[r] * wac;
    __syncthreads();

    const int warp = c >> 5, lane = c & 31;
#pragma unroll
    for (int rr = 0; rr < 4; rr++) {
        int r = warp * 4 + rr;
        float s = prod[r][lane] + prod[r][lane + 32] + prod[r][lane + 64] + prod[r][lane + 96];
#pragma unroll
        for (int o = 16; o > 0; o >>= 1) s += __shfl_xor_sync(0xffffffff, s, o);
        if (lane == 0) es_s[r] = __expf(s);
    }
    __syncthreads();

    const float bav = b_av[c];
#pragma unroll
    for (int r = 0; r < 16; r++) acc[r] = bav;
#pragma unroll 4
    for (int t = 0; t < DQ; t++) {
        float w = W_av[t * DQ + c];
#pragma unroll
        for (int r = 0; r < 16; r++) acc[r] += hr[r][t] * w;
    }
#pragma unroll
    for (int r = 0; r < 16; r++)
        d_U[(size_t)(j0 + r) * UW + c] = __float2half(es_s[r] * acc[r]);
    if (c < 32) {
#pragma unroll
        for (int r = 0; r < 16; r++)
            d_U[(size_t)(j0 + r) * UW + 128 + c] = __float2half(c == 0 ? es_s[r] : 0.f);
    }
}

// ---------------- 4. split-K fp16 GEMM: part[s] = G[:, ks:+1024] @ U[ks:+1024, :] ----------------
// BM=64, BN=160, BK=32. Grid (64 M-tiles, SPLITK) = 256 blocks, 128 threads.
// 4 warps as 2(M) x 2(N): warp tile 32x80.
__global__ __launch_bounds__(128) void gemm_kernel()
{
    __shared__ __half As[2][64][40];   // pad 40 elems: conflict-free ldmatrix
    __shared__ __half Bs[2][32][168];  // pad 168: conflict-free ldmatrix.trans
    const int tid = threadIdx.x;
    const int m0 = blockIdx.x * 64;
    const size_t ks = (size_t)blockIdx.y * (NN / SPLITK);
    const int warp = tid >> 5, lane = tid & 31;
    const int wm = (warp & 1) * 32, wn = (warp >> 1) * 80;

    float acc[2][10][4];
#pragma unroll
    for (int mi = 0; mi < 2; mi++)
#pragma unroll
        for (int i = 0; i < 10; i++)
            acc[mi][i][0] = acc[mi][i][1] = acc[mi][i][2] = acc[mi][i][3] = 0.f;

    // A tile: 64x32 = 256 uint4 segs, 2 per thread (tid, tid+128)
    const int ar0 = tid >> 2,          ac0 = (tid & 3) * 8;
    const int ar1 = (tid + 128) >> 2,  ac1 = ((tid + 128) & 3) * 8;
    // B tile: 32x160 = 640 uint4 segs, 5 per thread
    int brow[5], bcol[5];
#pragma unroll
    for (int i = 0; i < 5; i++) {
        int s = tid + 128 * i;
        brow[i] = s / 20;
        bcol[i] = (s % 20) * 8;
    }

    const __half* Ag = d_G + (size_t)m0 * NN + ks;
    const __half* Ug = d_U + ks * UW;

    uint4 aF0, aF1, bF[5];
    // prologue: stage 0
    aF0 = *(const uint4*)(Ag + (size_t)ar0 * NN + ac0);
    aF1 = *(const uint4*)(Ag + (size_t)ar1 * NN + ac1);
#pragma unroll
    for (int i = 0; i < 5; i++)
        bF[i] = *(const uint4*)(Ug + (size_t)brow[i] * UW + bcol[i]);
    *(uint4*)&As[0][ar0][ac0] = aF0;
    *(uint4*)&As[0][ar1][ac1] = aF1;
#pragma unroll
    for (int i = 0; i < 5; i++)
        *(uint4*)&Bs[0][brow[i]][bcol[i]] = bF[i];
    __syncthreads();

#pragma unroll 1
    for (int s = 0; s < 32; s++) {
        const int buf = s & 1;
        if (s + 1 < 32) {  // prefetch next k-tile to regs
            const size_t ko = (size_t)(s + 1) * 32;
            aF0 = *(const uint4*)(Ag + (size_t)ar0 * NN + ko + ac0);
            aF1 = *(const uint4*)(Ag + (size_t)ar1 * NN + ko + ac1);
            const __half* U2 = Ug + ko * UW;
#pragma unroll
            for (int i = 0; i < 5; i++)
                bF[i] = *(const uint4*)(U2 + (size_t)brow[i] * UW + bcol[i]);
        }
#pragma unroll
        for (int kk = 0; kk < 2; kk++) {
            uint32_t a0[4], a1[4];
            ldsm_x4(a0[0], a0[1], a0[2], a0[3],
                    smem_u32(&As[buf][wm + (lane & 15)][kk * 16 + (lane >> 4) * 8]));
            ldsm_x4(a1[0], a1[1], a1[2], a1[3],
                    smem_u32(&As[buf][wm + 16 + (lane & 15)][kk * 16 + (lane >> 4) * 8]));
#pragma unroll
            for (int nf = 0; nf < 5; nf++) {
                uint32_t b0, b1, b2, b3;
                ldsm_x4t(b0, b1, b2, b3,
                         smem_u32(&Bs[buf][kk * 16 + (lane & 15)][wn + nf * 16 + (lane >> 4) * 8]));
                float* c00 = acc[0][2 * nf];
                float* c01 = acc[0][2 * nf + 1];
                float* c10 = acc[1][2 * nf];
                float* c11 = acc[1][2 * nf + 1];
                mma_f16(c00[0], c00[1], c00[2], c00[3], a0[0], a0[1], a0[2], a0[3], b0, b1);
                mma_f16(c01[0], c01[1], c01[2], c01[3], a0[0], a0[1], a0[2], a0[3], b2, b3);
                mma_f16(c10[0], c10[1], c10[2], c10[3], a1[0], a1[1], a1[2], a1[3], b0, b1);
                mma_f16(c11[0], c11[1], c11[2], c11[3], a1[0], a1[1], a1[2], a1[3], b2, b3);
            }
        }
        if (s + 1 < 32) {
            const int nb = (s + 1) & 1;
            *(uint4*)&As[nb][ar0][ac0] = aF0;
            *(uint4*)&As[nb][ar1][ac1] = aF1;
#pragma unroll
            for (int i = 0; i < 5; i++)
                *(uint4*)&Bs[nb][brow[i]][bcol[i]] = bF[i];
        }
        __syncthreads();
    }

    // epilogue: write split partials (no atomics -> deterministic)
    const int g = lane >> 2, tg = lane & 3;
    float* P = d_part + ((size_t)blockIdx.y * NN + m0 + wm) * UW + wn;
#pragma unroll
    for (int mi = 0; mi < 2; mi++) {
#pragma unroll
        for (int nf = 0; nf < 10; nf++) {
            int col = nf * 8 + tg * 2;
            int r0 = mi * 16 + g;
            *(float2*)&P[(size_t)r0 * UW + col] =
                make_float2(acc[mi][nf][0], acc[mi][nf][1]);
            *(float2*)&P[(size_t)(r0 + 8) * UW + col] =
                make_float2(acc[mi][nf][2], acc[mi][nf][3]);
        }
    }
}

// ---------------- 5. reduce splits + softmax normalize: h = num / den ----------------
__global__ __launch_bounds__(128) void norm_kernel()
{
    const int i = blockIdx.x, c = threadIdx.x;
    const float* p = d_part + (size_t)i * UW;
    float num = 0.f, den = 0.f;
#pragma unroll
    for (int s = 0; s < SPLITK; s++) {
        num += p[(size_t)s * NN * UW + c];
        den += p[(size_t)s * NN * UW + 128];
    }
    d_h[(size_t)i * DQ + c] = num / den;
}

// ---------------- 6. decode: out = h @ W_dec + b_dec (+mask) ----------------
__global__ __launch_bounds__(128) void decode_kernel(
    const float* __restrict__ W_dec, const float* __restrict__ b_dec,
    const int* __restrict__ mask, float* __restrict__ out)
{
    const int i = blockIdx.x, c = threadIdx.x;
    __shared__ float red[128];
    red[c] = d_h[(size_t)i * DQ + c] * W_dec[c];
    __syncthreads();
    for (int off = 64; off > 0; off >>= 1) {
        if (c < off) red[c] += red[c + off];
        __syncthreads();
    }
    if (c == 0)
        out[i] = (mask[i] == 0) ? __int_as_float(0xff800000) : (red[0] + b_dec[0]);
}

// ---------------- launch ----------------
extern "C" void kernel_launch(void* const* d_in, const int* in_sizes, int n_in,
                              void* d_out, int out_size)
{
    const float* x      = (const float*)d_in[0];
    const float* comms  = (const float*)d_in[1];
    const float* trans  = (const float*)d_in[2];
    const int*   mask   = (const int*)d_in[3];
    const float* W_enc  = (const float*)d_in[4];
    const float* b_enc  = (const float*)d_in[5];
    const float* W_ad   = (const float*)d_in[6];
    const float* b_ad   = (const float*)d_in[7];
    const float* w_att  = (const float*)d_in[8];
    // d_in[9] = b_att: cancels in row-softmax, unused
    const float* W_av   = (const float*)d_in[10];
    const float* b_av   = (const float*)d_in[11];
    const float* W_dec  = (const float*)d_in[12];
    const float* b_dec  = (const float*)d_in[13];
    float* out = (float*)d_out;

    encode_kernel<<<NN / 16, 128>>>(x, comms, W_enc, b_enc);
    buildG_kernel<<<dim3(NN / 32, NN / 32), dim3(32, 8)>>>(trans);

    for (int k = 0; k < 3; k++) {
        computeU_kernel<<<NN / 16, 128>>>(W_ad + (size_t)k * DQ * DQ,
                                          b_ad + (size_t)k * DQ,
                                          w_att + (size_t)k * 2 * DQ,   // wa = first half
                                          W_av + (size_t)k * DQ * DQ,
                                          b_av + (size_t)k * DQ);
        gemm_kernel<<<dim3(NN / 64, SPLITK), 128>>>();
        norm_kernel<<<NN, 128>>>();
    }
    decode_kernel<<<NN, 128>>>(W_dec, b_dec, mask, out);
}

// round 4
// speedup vs baseline: 1.4577x; 1.1306x over previous
#include <cuda_runtime.h>
#include <cuda_fp16.h>
#include <cstdint>

#define NN 4096
#define DQ 128
#define UW 160          // padded U width (128 v-cols + 1 denom col + pad)
#define SPLITK 8
#define KCHUNK (NN / SPLITK)   // 512
#define KITERS (KCHUNK / 32)   // 16

// ---------------- scratch (static device globals; no allocation) ----------------
__device__ __half d_E[(size_t)NN * NN];                 // 32 MB: exp(trans) fp16, NOT transposed
__device__ float  d_h[(size_t)NN * DQ];                 // 2 MB : encoder output (layer 0 input)
__device__ __half d_U[(size_t)NN * UW];                 // 1.25MB: e^{sa}*v | e^{sa} | 0
__device__ float  d_part[(size_t)SPLITK * NN * UW];     // 21 MB: split-K partials

// ---------------- PTX helpers ----------------
__device__ __forceinline__ uint32_t smem_u32(const void* p) {
    return (uint32_t)__cvta_generic_to_shared(p);
}
__device__ __forceinline__ void ldsm_x4t(uint32_t& r0, uint32_t& r1, uint32_t& r2, uint32_t& r3, uint32_t a) {
    asm volatile("ldmatrix.sync.aligned.m8n8.x4.trans.shared.b16 {%0,%1,%2,%3},[%4];"
                 : "=r"(r0), "=r"(r1), "=r"(r2), "=r"(r3) : "r"(a));
}
__device__ __forceinline__ void mma_f16(float& d0, float& d1, float& d2, float& d3,
                                        uint32_t a0, uint32_t a1, uint32_t a2, uint32_t a3,
                                        uint32_t b0, uint32_t b1) {
    asm volatile(
        "mma.sync.aligned.m16n8k16.row.col.f32.f16.f16.f32 "
        "{%0,%1,%2,%3},{%4,%5,%6,%7},{%8,%9},{%0,%1,%2,%3};"
        : "+f"(d0), "+f"(d1), "+f"(d2), "+f"(d3)
        : "r"(a0), "r"(a1), "r"(a2), "r"(a3), "r"(b0), "r"(b1));
}
__device__ __forceinline__ void cp16(uint32_t dst, const void* src) {
    asm volatile("cp.async.cg.shared.global [%0], [%1], 16;" :: "r"(dst), "l"(src));
}

// ---------------- 1. encode: h = [x|comms] @ W_enc + b_enc ----------------
__global__ __launch_bounds__(128) void encode_kernel(
    const float* __restrict__ x, const float* __restrict__ comms,
    const float* __restrict__ W_enc, const float* __restrict__ b_enc)
{
    const int i0 = blockIdx.x * 16;
    const int c = threadIdx.x;
    __shared__ float in[16][96];
    for (int idx = c; idx < 16 * 64; idx += 128) {
        int r = idx >> 6, t = idx & 63;
        in[r][t] = x[(size_t)(i0 + r) * 64 + t];
    }
    for (int idx = c; idx < 16 * 32; idx += 128) {
        int r = idx >> 5, t = idx & 31;
        in[r][64 + t] = comms[(size_t)(i0 + r) * 32 + t];
    }
    __syncthreads();
    float acc[16];
    const float be = b_enc[c];
#pragma unroll
    for (int r = 0; r < 16; r++) acc[r] = be;
#pragma unroll 4
    for (int t = 0; t < 96; t++) {
        float w = W_enc[t * DQ + c];
#pragma unroll
        for (int r = 0; r < 16; r++) acc[r] += in[r][t] * w;
    }
#pragma unroll
    for (int r = 0; r < 16; r++) d_h[(size_t)(i0 + r) * DQ + c] = acc[r];
}

// ---------------- 2. build E = exp(trans) elementwise (no transpose) ----------------
__global__ __launch_bounds__(256) void buildE_kernel(const float* __restrict__ trans)
{
    const size_t idx = ((size_t)blockIdx.x * 256 + threadIdx.x) * 8;
    float4 v0 = *(const float4*)(trans + idx);
    float4 v1 = *(const float4*)(trans + idx + 4);
    float e[8];
    e[0] = (v0.x == 0.f) ? 0.f : __expf(v0.x);
    e[1] = (v0.y == 0.f) ? 0.f : __expf(v0.y);
    e[2] = (v0.z == 0.f) ? 0.f : __expf(v0.z);
    e[3] = (v0.w == 0.f) ? 0.f : __expf(v0.w);
    e[4] = (v1.x == 0.f) ? 0.f : __expf(v1.x);
    e[5] = (v1.y == 0.f) ? 0.f : __expf(v1.y);
    e[6] = (v1.z == 0.f) ? 0.f : __expf(v1.z);
    e[7] = (v1.w == 0.f) ? 0.f : __expf(v1.w);
    __half2 h2[4];
#pragma unroll
    for (int i = 0; i < 4; i++)
        h2[i] = __floats2half2_rn(e[2 * i], e[2 * i + 1]);
    *(uint4*)(d_E + idx) = *(uint4*)h2;
}

// ---------------- 3. per-layer U (fp16); input = d_h (layer 0) or split partials ----------------
// U[j][c<128] = exp(sa_j)*v[j][c]; U[j][128] = exp(sa_j); U[j][129..159] = 0
__global__ __launch_bounds__(128) void computeU_kernel(
    const float* __restrict__ W_ad, const float* __restrict__ b_ad,
    const float* __restrict__ wa,   const float* __restrict__ W_av,
    const float* __restrict__ b_av, int use_part)
{
    const int j0 = blockIdx.x * 16;
    const int c = threadIdx.x;
    __shared__ float hr[16][DQ];
    __shared__ float prod[16][DQ + 1];
    __shared__ float es_s[16];
    __shared__ float den[16];

    if (!use_part) {
#pragma unroll
        for (int r = 0; r < 16; r++) hr[r][c] = d_h[(size_t)(j0 + r) * DQ + c];
    } else {
        if (c < 16) {
            float d = 0.f;
#pragma unroll
            for (int s = 0; s < SPLITK; s++)
                d += d_part[(size_t)s * NN * UW + (size_t)(j0 + c) * UW + 128];
            den[c] = d;
        }
#pragma unroll
        for (int r = 0; r < 16; r++) {
            float num = 0.f;
#pragma unroll
            for (int s = 0; s < SPLITK; s++)
                num += d_part[(size_t)s * NN * UW + (size_t)(j0 + r) * UW + c];
            hr[r][c] = num;   // divide after sync
        }
        __syncthreads();
#pragma unroll
        for (int r = 0; r < 16; r++) hr[r][c] = hr[r][c] / den[r];
    }
    __syncthreads();

    float acc[16];
    const float bad = b_ad[c];
#pragma unroll
    for (int r = 0; r < 16; r++) acc[r] = bad;
#pragma unroll 4
    for (int t = 0; t < DQ; t++) {
        float w = W_ad[t * DQ + c];
#pragma unroll
        for (int r = 0; r < 16; r++) acc[r] += hr[r][t] * w;
    }
    const float wac = wa[c];
#pragma unroll
    for (int r = 0; r < 16; r++) prod[r][c] = acc[r] * wac;
    __syncthreads();

    const int warp = c >> 5, lane = c & 31;
#pragma unroll
    for (int rr = 0; rr < 4; rr++) {
        int r = warp * 4 + rr;
        float s = prod[r][lane] + prod[r][lane + 32] + prod[r][lane + 64] + prod[r][lane + 96];
#pragma unroll
        for (int o = 16; o > 0; o >>= 1) s += __shfl_xor_sync(0xffffffff, s, o);
        if (lane == 0) es_s[r] = __expf(s);
    }
    __syncthreads();

    const float bav = b_av[c];
#pragma unroll
    for (int r = 0; r < 16; r++) acc[r] = bav;
#pragma unroll 4
    for (int t = 0; t < DQ; t++) {
        float w = W_av[t * DQ + c];
#pragma unroll
        for (int r = 0; r < 16; r++) acc[r] += hr[r][t] * w;
    }
#pragma unroll
    for (int r = 0; r < 16; r++)
        d_U[(size_t)(j0 + r) * UW + c] = __float2half(es_s[r] * acc[r]);
    if (c < 32) {
#pragma unroll
        for (int r = 0; r < 16; r++)
            d_U[(size_t)(j0 + r) * UW + 128 + c] = __float2half(c == 0 ? es_s[r] : 0.f);
    }
}

// ---------------- 4. split-K fp16 GEMM with 3-stage cp.async pipeline ----------------
// part[s][i][n] = sum_{j in chunk s} E[j][i] * U[j][n]
// BM=64, BN=160, BK=32. Grid (64 M-tiles, SPLITK=8) = 512 blocks, 128 threads.
// A (E slab) is k-major in smem -> A frags via ldmatrix.trans.
#define AS_STRIDE 72    // 144B rows: conflict-free trans ldsm
#define BS_STRIDE 168   // 336B rows: conflict-free trans ldsm

__global__ __launch_bounds__(128) void gemm_kernel()
{
    __shared__ __half As[3][32][AS_STRIDE];
    __shared__ __half Bs[3][32][BS_STRIDE];

    const int tid = threadIdx.x;
    const int m0 = blockIdx.x * 64;
    const size_t ks = (size_t)blockIdx.y * KCHUNK;
    const int warp = tid >> 5, lane = tid & 31;
    const int wm = (warp & 1) * 32, wn = (warp >> 1) * 80;

    float acc[2][10][4];
#pragma unroll
    for (int mi = 0; mi < 2; mi++)
#pragma unroll
        for (int i = 0; i < 10; i++)
            acc[mi][i][0] = acc[mi][i][1] = acc[mi][i][2] = acc[mi][i][3] = 0.f;

    // cp.async source/dest index precompute
    // A: 32 rows x 64 halfs = 256 16B-chunks; 2 per thread
    const int ar0 = tid >> 3,           ac0 = (tid & 7) * 8;
    const int ar1 = (tid + 128) >> 3,   ac1 = ((tid + 128) & 7) * 8;
    // B: 32 rows x 160 halfs = 640 16B-chunks; 5 per thread
    int brow[5], bcol[5];
#pragma unroll
    for (int i = 0; i < 5; i++) {
        int s = tid + 128 * i;
        brow[i] = s / 20;
        bcol[i] = (s % 20) * 8;
    }

    const __half* Eg = d_E + ks * NN + m0;   // E[k][m]
    const __half* Ug = d_U + ks * UW;        // U[k][n]

#define ISSUE_STAGE(buf, kbase)                                                   \
    do {                                                                          \
        const __half* Ea = Eg + (size_t)(kbase) * NN;                             \
        const __half* Ua = Ug + (size_t)(kbase) * UW;                             \
        cp16(smem_u32(&As[buf][ar0][ac0]), Ea + (size_t)ar0 * NN + ac0);          \
        cp16(smem_u32(&As[buf][ar1][ac1]), Ea + (size_t)ar1 * NN + ac1);          \
        _Pragma("unroll")                                                         \
        for (int i = 0; i < 5; i++)                                               \
            cp16(smem_u32(&Bs[buf][brow[i]][bcol[i]]),                            \
                 Ua + (size_t)brow[i] * UW + bcol[i]);                            \
        asm volatile("cp.async.commit_group;");                                   \
    } while (0)

    // prologue: fill 3 stages
    ISSUE_STAGE(0, 0);
    ISSUE_STAGE(1, 32);
    ISSUE_STAGE(2, 64);

#pragma unroll 1
    for (int it = 0; it < KITERS; it++) {
        const int buf = it % 3;
        asm volatile("cp.async.wait_group 2;");
        __syncthreads();

#pragma unroll
        for (int kk = 0; kk < 2; kk++) {
            // A frags via trans-ldsm from k-major smem
            const int arow = kk * 16 + (lane & 7) + ((lane >> 4) << 3);
            const int acb = wm + ((lane >> 3) & 1) * 8;
            uint32_t a0[4], a1[4];
            ldsm_x4t(a0[0], a0[1], a0[2], a0[3], smem_u32(&As[buf][arow][acb]));
            ldsm_x4t(a1[0], a1[1], a1[2], a1[3], smem_u32(&As[buf][arow][acb + 16]));
#pragma unroll
            for (int nf = 0; nf < 5; nf++) {
                uint32_t b0, b1, b2, b3;
                ldsm_x4t(b0, b1, b2, b3,
                         smem_u32(&Bs[buf][kk * 16 + (lane & 15)][wn + nf * 16 + (lane >> 4) * 8]));
                float* c00 = acc[0][2 * nf];
                float* c01 = acc[0][2 * nf + 1];
                float* c10 = acc[1][2 * nf];
                float* c11 = acc[1][2 * nf + 1];
                mma_f16(c00[0], c00[1], c00[2], c00[3], a0[0], a0[1], a0[2], a0[3], b0, b1);
                mma_f16(c01[0], c01[1], c01[2], c01[3], a0[0], a0[1], a0[2], a0[3], b2, b3);
                mma_f16(c10[0], c10[1], c10[2], c10[3], a1[0], a1[1], a1[2], a1[3], b0, b1);
                mma_f16(c11[0], c11[1], c11[2], c11[3], a1[0], a1[1], a1[2], a1[3], b2, b3);
            }
        }
        __syncthreads();
        if (it + 3 < KITERS) ISSUE_STAGE(buf, (it + 3) * 32);
    }

    // epilogue: write split partials (no atomics -> deterministic)
    const int g = lane >> 2, tg = lane & 3;
    float* P = d_part + ((size_t)blockIdx.y * NN + m0 + wm) * UW + wn;
#pragma unroll
    for (int mi = 0; mi < 2; mi++) {
#pragma unroll
        for (int nf = 0; nf < 10; nf++) {
            int col = nf * 8 + tg * 2;
            int r0 = mi * 16 + g;
            *(float2*)&P[(size_t)r0 * UW + col] =
                make_float2(acc[mi][nf][0], acc[mi][nf][1]);
            *(float2*)&P[(size_t)(r0 + 8) * UW + col] =
                make_float2(acc[mi][nf][2], acc[mi][nf][3]);
        }
    }
#undef ISSUE_STAGE
}

// ---------------- 5. decode: out = (num @ W_dec)/den + b_dec (+mask) ----------------
__global__ __launch_bounds__(128) void decode_kernel(
    const float* __restrict__ W_dec, const float* __restrict__ b_dec,
    const int* __restrict__ mask, float* __restrict__ out)
{
    const int i = blockIdx.x, c = threadIdx.x;
    __shared__ float red[128];
    float num = 0.f, den = 0.f;
#pragma unroll
    for (int s = 0; s < SPLITK; s++) {
        const float* p = d_part + (size_t)s * NN * UW + (size_t)i * UW;
        num += p[c];
        den += p[128];   // broadcast load, all threads same addr
    }
    red[c] = num * W_dec[c];
    __syncthreads();
    for (int off = 64; off > 0; off >>= 1) {
        if (c < off) red[c] += red[c + off];
        __syncthreads();
    }
    if (c == 0)
        out[i] = (mask[i] == 0) ? __int_as_float(0xff800000)
                                : (red[0] / den + b_dec[0]);
}

// ---------------- launch ----------------
extern "C" void kernel_launch(void* const* d_in, const int* in_sizes, int n_in,
                              void* d_out, int out_size)
{
    const float* x      = (const float*)d_in[0];
    const float* comms  = (const float*)d_in[1];
    const float* trans  = (const float*)d_in[2];
    const int*   mask   = (const int*)d_in[3];
    const float* W_enc  = (const float*)d_in[4];
    const float* b_enc  = (const float*)d_in[5];
    const float* W_ad   = (const float*)d_in[6];
    const float* b_ad   = (const float*)d_in[7];
    const float* w_att  = (const float*)d_in[8];
    // d_in[9] = b_att: cancels in row-softmax, unused
    const float* W_av   = (const float*)d_in[10];
    const float* b_av   = (const float*)d_in[11];
    const float* W_dec  = (const float*)d_in[12];
    const float* b_dec  = (const float*)d_in[13];
    float* out = (float*)d_out;

    encode_kernel<<<NN / 16, 128>>>(x, comms, W_enc, b_enc);
    buildE_kernel<<<(NN * (size_t)NN) / (256 * 8), 256>>>(trans);

    for (int k = 0; k < 3; k++) {
        computeU_kernel<<<NN / 16, 128>>>(W_ad + (size_t)k * DQ * DQ,
                                          b_ad + (size_t)k * DQ,
                                          w_att + (size_t)k * 2 * DQ,   // wa = first half
                                          W_av + (size_t)k * DQ * DQ,
                                          b_av + (size_t)k * DQ,
                                          k > 0);
        gemm_kernel<<<dim3(NN / 64, SPLITK), 128>>>();
    }
    decode_kernel<<<NN, 128>>>(W_dec, b_dec, mask, out);
}

// round 5
// speedup vs baseline: 1.4851x; 1.0188x over previous
#include <cuda_runtime.h>
#include <cuda_fp16.h>
#include <cstdint>

#define NN 4096
#define DQ 128
#define UW 160          // padded U width (128 v-cols + 1 denom col + pad)
#define SPLITK 16
#define KCHUNK (NN / SPLITK)   // 256
#define KITERS (KCHUNK / 32)   // 8

// ---------------- scratch (static device globals; no allocation) ----------------
__device__ __half d_E[(size_t)NN * NN];                 // 32 MB: exp(trans) fp16, k-major
__device__ float  d_h[(size_t)NN * DQ];                 // encoder output (layer 0 input)
__device__ __half d_U[(size_t)NN * UW];                 // e^{sa}*v | e^{sa} | 0
__device__ float  d_part[(size_t)SPLITK * NN * UW];     // 42 MB: split-K partials (reused as GEMV scratch)
__device__ float  d_uvec[NN];                           // layer3: e^{sa}*(v . W_dec)
__device__ float  d_evec[NN];                           // layer3: e^{sa}

// ---------------- PTX helpers ----------------
__device__ __forceinline__ uint32_t smem_u32(const void* p) {
    return (uint32_t)__cvta_generic_to_shared(p);
}
__device__ __forceinline__ void ldsm_x4t(uint32_t& r0, uint32_t& r1, uint32_t& r2, uint32_t& r3, uint32_t a) {
    asm volatile("ldmatrix.sync.aligned.m8n8.x4.trans.shared.b16 {%0,%1,%2,%3},[%4];"
                 : "=r"(r0), "=r"(r1), "=r"(r2), "=r"(r3) : "r"(a));
}
__device__ __forceinline__ void mma_f16(float& d0, float& d1, float& d2, float& d3,
                                        uint32_t a0, uint32_t a1, uint32_t a2, uint32_t a3,
                                        uint32_t b0, uint32_t b1) {
    asm volatile(
        "mma.sync.aligned.m16n8k16.row.col.f32.f16.f16.f32 "
        "{%0,%1,%2,%3},{%4,%5,%6,%7},{%8,%9},{%0,%1,%2,%3};"
        : "+f"(d0), "+f"(d1), "+f"(d2), "+f"(d3)
        : "r"(a0), "r"(a1), "r"(a2), "r"(a3), "r"(b0), "r"(b1));
}
__device__ __forceinline__ void cp16(uint32_t dst, const void* src) {
    asm volatile("cp.async.cg.shared.global [%0], [%1], 16;" :: "r"(dst), "l"(src));
}

// ---------------- 1. encode: h = [x|comms] @ W_enc + b_enc ----------------
__global__ __launch_bounds__(128) void encode_kernel(
    const float* __restrict__ x, const float* __restrict__ comms,
    const float* __restrict__ W_enc, const float* __restrict__ b_enc)
{
    const int i0 = blockIdx.x * 16;
    const int c = threadIdx.x;
    __shared__ float in[16][96];
    for (int idx = c; idx < 16 * 64; idx += 128) {
        int r = idx >> 6, t = idx & 63;
        in[r][t] = x[(size_t)(i0 + r) * 64 + t];
    }
    for (int idx = c; idx < 16 * 32; idx += 128) {
        int r = idx >> 5, t = idx & 31;
        in[r][64 + t] = comms[(size_t)(i0 + r) * 32 + t];
    }
    __syncthreads();
    float acc[16];
    const float be = b_enc[c];
#pragma unroll
    for (int r = 0; r < 16; r++) acc[r] = be;
#pragma unroll 4
    for (int t = 0; t < 96; t++) {
        float w = W_enc[t * DQ + c];
#pragma unroll
        for (int r = 0; r < 16; r++) acc[r] += in[r][t] * w;
    }
#pragma unroll
    for (int r = 0; r < 16; r++) d_h[(size_t)(i0 + r) * DQ + c] = acc[r];
}

// ---------------- 2. build E = exp(trans) elementwise (no transpose) ----------------
__global__ __launch_bounds__(256) void buildE_kernel(const float* __restrict__ trans)
{
    const size_t idx = ((size_t)blockIdx.x * 256 + threadIdx.x) * 8;
    float4 v0 = *(const float4*)(trans + idx);
    float4 v1 = *(const float4*)(trans + idx + 4);
    float e[8];
    e[0] = (v0.x == 0.f) ? 0.f : __expf(v0.x);
    e[1] = (v0.y == 0.f) ? 0.f : __expf(v0.y);
    e[2] = (v0.z == 0.f) ? 0.f : __expf(v0.z);
    e[3] = (v0.w == 0.f) ? 0.f : __expf(v0.w);
    e[4] = (v1.x == 0.f) ? 0.f : __expf(v1.x);
    e[5] = (v1.y == 0.f) ? 0.f : __expf(v1.y);
    e[6] = (v1.z == 0.f) ? 0.f : __expf(v1.z);
    e[7] = (v1.w == 0.f) ? 0.f : __expf(v1.w);
    __half2 h2[4];
#pragma unroll
    for (int i = 0; i < 4; i++)
        h2[i] = __floats2half2_rn(e[2 * i], e[2 * i + 1]);
    *(uint4*)(d_E + idx) = *(uint4*)h2;
}

// ---------------- 3. per-layer U; fused dual-weight pass ----------------
// Input: d_h (layer 0) or split partials (later layers, incl. normalize).
// Output: d_U planes, OR (final layer, W_dec != null) d_uvec/d_evec.
__global__ __launch_bounds__(128) void computeU_kernel(
    const float* __restrict__ W_ad, const float* __restrict__ b_ad,
    const float* __restrict__ wa,   const float* __restrict__ W_av,
    const float* __restrict__ b_av, int use_part,
    const float* __restrict__ W_dec)
{
    const int j0 = blockIdx.x * 16;
    const int c = threadIdx.x;
    __shared__ float hr[16][DQ];
    __shared__ float prod[16][DQ + 1];
    __shared__ float es_s[16];
    __shared__ float den[16];
    __shared__ float vdot[16];

    if (!use_part) {
#pragma unroll
        for (int r = 0; r < 16; r++) hr[r][c] = d_h[(size_t)(j0 + r) * DQ + c];
    } else {
        if (c < 16) {
            float d = 0.f;
#pragma unroll
            for (int s = 0; s < SPLITK; s++)
                d += d_part[(size_t)s * NN * UW + (size_t)(j0 + c) * UW + 128];
            den[c] = d;
        }
#pragma unroll
        for (int r = 0; r < 16; r++) {
            float num = 0.f;
#pragma unroll
            for (int s = 0; s < SPLITK; s++)
                num += d_part[(size_t)s * NN * UW + (size_t)(j0 + r) * UW + c];
            hr[r][c] = num;   // divide after sync
        }
        __syncthreads();
#pragma unroll
        for (int r = 0; r < 16; r++) hr[r][c] = hr[r][c] / den[r];
    }
    __syncthreads();

    // fused: att (W_ad) and v (W_av) accumulated in one pass over hr
    float acc_d[16], acc_v[16];
    const float bad = b_ad[c], bav = b_av[c];
#pragma unroll
    for (int r = 0; r < 16; r++) { acc_d[r] = bad; acc_v[r] = bav; }
#pragma unroll 2
    for (int t = 0; t < DQ; t++) {
        float wd = W_ad[t * DQ + c];
        float wv = W_av[t * DQ + c];
#pragma unroll
        for (int r = 0; r < 16; r++) {
            acc_d[r] += hr[r][t] * wd;
            acc_v[r] += hr[r][t] * wv;
        }
    }

    const float wac = wa[c];
#pragma unroll
    for (int r = 0; r < 16; r++) prod[r][c] = acc_d[r] * wac;
    __syncthreads();

    const int warp = c >> 5, lane = c & 31;
#pragma unroll
    for (int rr = 0; rr < 4; rr++) {
        int r = warp * 4 + rr;
        float s = prod[r][lane] + prod[r][lane + 32] + prod[r][lane + 64] + prod[r][lane + 96];
#pragma unroll
        for (int o = 16; o > 0; o >>= 1) s += __shfl_xor_sync(0xffffffff, s, o);
        if (lane == 0) es_s[r] = __expf(s);
    }
    __syncthreads();

    if (W_dec == nullptr) {
#pragma unroll
        for (int r = 0; r < 16; r++)
            d_U[(size_t)(j0 + r) * UW + c] = __float2half(es_s[r] * acc_v[r]);
        if (c < 32) {
#pragma unroll
            for (int r = 0; r < 16; r++)
                d_U[(size_t)(j0 + r) * UW + 128 + c] = __float2half(c == 0 ? es_s[r] : 0.f);
        }
    } else {
        // final layer: reduce v . W_dec per row -> scalar u_j
        const float wdc = W_dec[c];
#pragma unroll
        for (int r = 0; r < 16; r++) prod[r][c] = acc_v[r] * wdc;
        __syncthreads();
#pragma unroll
        for (int rr = 0; rr < 4; rr++) {
            int r = warp * 4 + rr;
            float s = prod[r][lane] + prod[r][lane + 32] + prod[r][lane + 64] + prod[r][lane + 96];
#pragma unroll
            for (int o = 16; o > 0; o >>= 1) s += __shfl_xor_sync(0xffffffff, s, o);
            if (lane == 0) vdot[r] = s;
        }
        __syncthreads();
        if (c < 16) {
            d_uvec[j0 + c] = es_s[c] * vdot[c];
            d_evec[j0 + c] = es_s[c];
        }
    }
}

// ---------------- 4. split-K fp16 GEMM with 3-stage cp.async pipeline ----------------
// part[s][i][n] = sum_{j in chunk s} E[j][i] * U[j][n]
#define AS_STRIDE 72
#define BS_STRIDE 168

__global__ __launch_bounds__(128) void gemm_kernel()
{
    __shared__ __half As[3][32][AS_STRIDE];
    __shared__ __half Bs[3][32][BS_STRIDE];

    const int tid = threadIdx.x;
    const int m0 = blockIdx.x * 64;
    const size_t ks = (size_t)blockIdx.y * KCHUNK;
    const int warp = tid >> 5, lane = tid & 31;
    const int wm = (warp & 1) * 32, wn = (warp >> 1) * 80;

    float acc[2][10][4];
#pragma unroll
    for (int mi = 0; mi < 2; mi++)
#pragma unroll
        for (int i = 0; i < 10; i++)
            acc[mi][i][0] = acc[mi][i][1] = acc[mi][i][2] = acc[mi][i][3] = 0.f;

    const int ar0 = tid >> 3,           ac0 = (tid & 7) * 8;
    const int ar1 = (tid + 128) >> 3,   ac1 = ((tid + 128) & 7) * 8;
    int brow[5], bcol[5];
#pragma unroll
    for (int i = 0; i < 5; i++) {
        int s = tid + 128 * i;
        brow[i] = s / 20;
        bcol[i] = (s % 20) * 8;
    }

    const __half* Eg = d_E + ks * NN + m0;   // E[k][m]
    const __half* Ug = d_U + ks * UW;        // U[k][n]

#define ISSUE_STAGE(buf, kbase)                                                   \
    do {                                                                          \
        const __half* Ea = Eg + (size_t)(kbase) * NN;                             \
        const __half* Ua = Ug + (size_t)(kbase) * UW;                             \
        cp16(smem_u32(&As[buf][ar0][ac0]), Ea + (size_t)ar0 * NN + ac0);          \
        cp16(smem_u32(&As[buf][ar1][ac1]), Ea + (size_t)ar1 * NN + ac1);          \
        _Pragma("unroll")                                                         \
        for (int i = 0; i < 5; i++)                                               \
            cp16(smem_u32(&Bs[buf][brow[i]][bcol[i]]),                            \
                 Ua + (size_t)brow[i] * UW + bcol[i]);                            \
        asm volatile("cp.async.commit_group;");                                   \
    } while (0)

    ISSUE_STAGE(0, 0);
    ISSUE_STAGE(1, 32);
    ISSUE_STAGE(2, 64);

#pragma unroll 1
    for (int it = 0; it < KITERS; it++) {
        const int buf = it % 3;
        asm volatile("cp.async.wait_group 2;");
        __syncthreads();

#pragma unroll
        for (int kk = 0; kk < 2; kk++) {
            const int arow = kk * 16 + (lane & 7) + ((lane >> 4) << 3);
            const int acb = wm + ((lane >> 3) & 1) * 8;
            uint32_t a0[4], a1[4];
            ldsm_x4t(a0[0], a0[1], a0[2], a0[3], smem_u32(&As[buf][arow][acb]));
            ldsm_x4t(a1[0], a1[1], a1[2], a1[3], smem_u32(&As[buf][arow][acb + 16]));
#pragma unroll
            for (int nf = 0; nf < 5; nf++) {
                uint32_t b0, b1, b2, b3;
                ldsm_x4t(b0, b1, b2, b3,
                         smem_u32(&Bs[buf][kk * 16 + (lane & 15)][wn + nf * 16 + (lane >> 4) * 8]));
                float* c00 = acc[0][2 * nf];
                float* c01 = acc[0][2 * nf + 1];
                float* c10 = acc[1][2 * nf];
                float* c11 = acc[1][2 * nf + 1];
                mma_f16(c00[0], c00[1], c00[2], c00[3], a0[0], a0[1], a0[2], a0[3], b0, b1);
                mma_f16(c01[0], c01[1], c01[2], c01[3], a0[0], a0[1], a0[2], a0[3], b2, b3);
                mma_f16(c10[0], c10[1], c10[2], c10[3], a1[0], a1[1], a1[2], a1[3], b0, b1);
                mma_f16(c11[0], c11[1], c11[2], c11[3], a1[0], a1[1], a1[2], a1[3], b2, b3);
            }
        }
        __syncthreads();
        if (it + 3 < KITERS) ISSUE_STAGE(buf, (it + 3) * 32);
    }

    const int g = lane >> 2, tg = lane & 3;
    float* P = d_part + ((size_t)blockIdx.y * NN + m0 + wm) * UW + wn;
#pragma unroll
    for (int mi = 0; mi < 2; mi++) {
#pragma unroll
        for (int nf = 0; nf < 10; nf++) {
            int col = nf * 8 + tg * 2;
            int r0 = mi * 16 + g;
            *(float2*)&P[(size_t)r0 * UW + col] =
                make_float2(acc[mi][nf][0], acc[mi][nf][1]);
            *(float2*)&P[(size_t)(r0 + 8) * UW + col] =
                make_float2(acc[mi][nf][2], acc[mi][nf][3]);
        }
    }
#undef ISSUE_STAGE
}

// ---------------- 5. layer-3 GEMV: colsum of E weighted by u / e ----------------
// gnum[jc][i] = sum_{j in chunk jc} E[j][i]*u[j];  gden likewise with e[j].
// Scratch planes live in d_part (free after layer-2 computeU consumed it).
#define JCH 64          // rows per j-chunk
#define NJC (NN / JCH)  // 64 chunks
__global__ __launch_bounds__(256) void gemv_kernel()
{
    float* gnum = d_part;                // [NJC][NN]
    float* gden = d_part + (size_t)NJC * NN;
    const int i0 = blockIdx.x * 1024;
    const int j0 = blockIdx.y * JCH;
    const int t = threadIdx.x;
    __shared__ float su[JCH], sev[JCH];
    if (t < JCH) { su[t] = d_uvec[j0 + t]; sev[t] = d_evec[j0 + t]; }
    __syncthreads();

    float n0 = 0.f, n1 = 0.f, n2 = 0.f, n3 = 0.f;
    float e0 = 0.f, e1 = 0.f, e2 = 0.f, e3 = 0.f;
    const __half* Eb = d_E + (size_t)j0 * NN + i0 + 2 * t;
#pragma unroll 4
    for (int j = 0; j < JCH; j++) {
        const float u = su[j], ev = sev[j];
        const __half2 a = *(const __half2*)(Eb + (size_t)j * NN);
        const __half2 b = *(const __half2*)(Eb + (size_t)j * NN + 512);
        const float2 af = __half22float2(a);
        const float2 bf = __half22float2(b);
        n0 += af.x * u;  n1 += af.y * u;
        n2 += bf.x * u;  n3 += bf.y * u;
        e0 += af.x * ev; e1 += af.y * ev;
        e2 += bf.x * ev; e3 += bf.y * ev;
    }
    const size_t base = (size_t)blockIdx.y * NN + i0 + 2 * t;
    *(float2*)&gnum[base] = make_float2(n0, n1);
    *(float2*)&gnum[base + 512] = make_float2(n2, n3);
    *(float2*)&gden[base] = make_float2(e0, e1);
    *(float2*)&gden[base + 512] = make_float2(e2, e3);
}

// ---------------- 6. finalize: out = num/den + b_dec (+mask) ----------------
__global__ __launch_bounds__(128) void finalize_kernel(
    const float* __restrict__ b_dec, const int* __restrict__ mask,
    float* __restrict__ out)
{
    const float* gnum = d_part;
    const float* gden = d_part + (size_t)NJC * NN;
    const int i = blockIdx.x * 128 + threadIdx.x;
    float num = 0.f, den = 0.f;
#pragma unroll 8
    for (int jc = 0; jc < NJC; jc++) {
        num += gnum[(size_t)jc * NN + i];
        den += gden[(size_t)jc * NN + i];
    }
    out[i] = (mask[i] == 0) ? __int_as_float(0xff800000)
                            : (num / den + b_dec[0]);
}

// ---------------- launch ----------------
extern "C" void kernel_launch(void* const* d_in, const int* in_sizes, int n_in,
                              void* d_out, int out_size)
{
    const float* x      = (const float*)d_in[0];
    const float* comms  = (const float*)d_in[1];
    const float* trans  = (const float*)d_in[2];
    const int*   mask   = (const int*)d_in[3];
    const float* W_enc  = (const float*)d_in[4];
    const float* b_enc  = (const float*)d_in[5];
    const float* W_ad   = (const float*)d_in[6];
    const float* b_ad   = (const float*)d_in[7];
    const float* w_att  = (const float*)d_in[8];
    // d_in[9] = b_att: cancels in row-softmax, unused
    const float* W_av   = (const float*)d_in[10];
    const float* b_av   = (const float*)d_in[11];
    const float* W_dec  = (const float*)d_in[12];
    const float* b_dec  = (const float*)d_in[13];
    float* out = (float*)d_out;

    encode_kernel<<<NN / 16, 128>>>(x, comms, W_enc, b_enc);
    buildE_kernel<<<(NN * (size_t)NN) / (256 * 8), 256>>>(trans);

    for (int k = 0; k < 3; k++) {
        computeU_kernel<<<NN / 16, 128>>>(W_ad + (size_t)k * DQ * DQ,
                                          b_ad + (size_t)k * DQ,
                                          w_att + (size_t)k * 2 * DQ,   // wa = first half
                                          W_av + (size_t)k * DQ * DQ,
                                          b_av + (size_t)k * DQ,
                                          k > 0,
                                          (k == 2) ? W_dec : nullptr);
        if (k < 2)
            gemm_kernel<<<dim3(NN / 64, SPLITK), 128>>>();
    }
    gemv_kernel<<<dim3(4, NJC), 256>>>();
    finalize_kernel<<<NN / 128, 128>>>(b_dec, mask, out);
}

// round 7
// speedup vs baseline: 1.4988x; 1.0093x over previous
#include <cuda_runtime.h>
#include <cuda_fp16.h>
#include <cstdint>

#define NN 4096
#define DQ 128
#define UW 160          // padded U width (128 v-cols + 1 denom col + pad)
#define SPLITK 8
#define KCHUNK (NN / SPLITK)   // 512
#define KITERS (KCHUNK / 32)   // 16

// ---------------- scratch (static device globals; no allocation) ----------------
__device__ __half d_E[(size_t)NN * NN];                 // 32 MB: exp(trans) fp16, k-major
__device__ float  d_h[(size_t)NN * DQ];                 // encoder output (layer 0 input)
__device__ __half d_U[(size_t)NN * UW];                 // e^{sa}*v | e^{sa} | 0
__device__ float  d_part[(size_t)SPLITK * NN * UW];     // split-K partials (reused as GEMV scratch)
__device__ float  d_uvec[NN];                           // layer3: e^{sa}*(v . W_dec)
__device__ float  d_evec[NN];                           // layer3: e^{sa}

// ---------------- PTX helpers ----------------
__device__ __forceinline__ uint32_t smem_u32(const void* p) {
    return (uint32_t)__cvta_generic_to_shared(p);
}
__device__ __forceinline__ void ldsm_x4t(uint32_t& r0, uint32_t& r1, uint32_t& r2, uint32_t& r3, uint32_t a) {
    asm volatile("ldmatrix.sync.aligned.m8n8.x4.trans.shared.b16 {%0,%1,%2,%3},[%4];"
                 : "=r"(r0), "=r"(r1), "=r"(r2), "=r"(r3) : "r"(a));
}
__device__ __forceinline__ void mma_f16(float& d0, float& d1, float& d2, float& d3,
                                        uint32_t a0, uint32_t a1, uint32_t a2, uint32_t a3,
                                        uint32_t b0, uint32_t b1) {
    asm volatile(
        "mma.sync.aligned.m16n8k16.row.col.f32.f16.f16.f32 "
        "{%0,%1,%2,%3},{%4,%5,%6,%7},{%8,%9},{%0,%1,%2,%3};"
        : "+f"(d0), "+f"(d1), "+f"(d2), "+f"(d3)
        : "r"(a0), "r"(a1), "r"(a2), "r"(a3), "r"(b0), "r"(b1));
}
__device__ __forceinline__ void cp16(uint32_t dst, const void* src) {
    asm volatile("cp.async.cg.shared.global [%0], [%1], 16;" :: "r"(dst), "l"(src));
}

// ---------------- 1. encode: h = [x|comms] @ W_enc + b_enc ----------------
__global__ __launch_bounds__(128) void encode_kernel(
    const float* __restrict__ x, const float* __restrict__ comms,
    const float* __restrict__ W_enc, const float* __restrict__ b_enc)
{
    const int i0 = blockIdx.x * 16;
    const int c = threadIdx.x;
    __shared__ float in[16][96];
    for (int idx = c; idx < 16 * 64; idx += 128) {
        int r = idx >> 6, t = idx & 63;
        in[r][t] = x[(size_t)(i0 + r) * 64 + t];
    }
    for (int idx = c; idx < 16 * 32; idx += 128) {
        int r = idx >> 5, t = idx & 31;
        in[r][64 + t] = comms[(size_t)(i0 + r) * 32 + t];
    }
    __syncthreads();
    float acc[16];
    const float be = b_enc[c];
#pragma unroll
    for (int r = 0; r < 16; r++) acc[r] = be;
#pragma unroll 4
    for (int t = 0; t < 96; t++) {
        float w = W_enc[t * DQ + c];
#pragma unroll
        for (int r = 0; r < 16; r++) acc[r] += in[r][t] * w;
    }
#pragma unroll
    for (int r = 0; r < 16; r++) d_h[(size_t)(i0 + r) * DQ + c] = acc[r];
}

// ---------------- 2. build E = exp(trans) elementwise (no transpose) ----------------
__global__ __launch_bounds__(256) void buildE_kernel(const float* __restrict__ trans)
{
    const size_t idx = ((size_t)blockIdx.x * 256 + threadIdx.x) * 8;
    float4 v0 = *(const float4*)(trans + idx);
    float4 v1 = *(const float4*)(trans + idx + 4);
    float e[8];
    e[0] = (v0.x == 0.f) ? 0.f : __expf(v0.x);
    e[1] = (v0.y == 0.f) ? 0.f : __expf(v0.y);
    e[2] = (v0.z == 0.f) ? 0.f : __expf(v0.z);
    e[3] = (v0.w == 0.f) ? 0.f : __expf(v0.w);
    e[4] = (v1.x == 0.f) ? 0.f : __expf(v1.x);
    e[5] = (v1.y == 0.f) ? 0.f : __expf(v1.y);
    e[6] = (v1.z == 0.f) ? 0.f : __expf(v1.z);
    e[7] = (v1.w == 0.f) ? 0.f : __expf(v1.w);
    __half2 h2[4];
#pragma unroll
    for (int i = 0; i < 4; i++)
        h2[i] = __floats2half2_rn(e[2 * i], e[2 * i + 1]);
    *(uint4*)(d_E + idx) = *(uint4*)h2;
}

// ---------------- 3. per-layer U; fused dual-weight pass ----------------
__global__ __launch_bounds__(128) void computeU_kernel(
    const float* __restrict__ W_ad, const float* __restrict__ b_ad,
    const float* __restrict__ wa,   const float* __restrict__ W_av,
    const float* __restrict__ b_av, int use_part,
    const float* __restrict__ W_dec)
{
    const int j0 = blockIdx.x * 16;
    const int c = threadIdx.x;
    __shared__ float hr[16][DQ];
    __shared__ float prod[16][DQ + 1];
    __shared__ float es_s[16];
    __shared__ float den[16];
    __shared__ float vdot[16];

    if (!use_part) {
#pragma unroll
        for (int r = 0; r < 16; r++) hr[r][c] = d_h[(size_t)(j0 + r) * DQ + c];
    } else {
        if (c < 16) {
            float d = 0.f;
#pragma unroll
            for (int s = 0; s < SPLITK; s++)
                d += d_part[(size_t)s * NN * UW + (size_t)(j0 + c) * UW + 128];
            den[c] = d;
        }
#pragma unroll
        for (int r = 0; r < 16; r++) {
            float num = 0.f;
#pragma unroll
            for (int s = 0; s < SPLITK; s++)
                num += d_part[(size_t)s * NN * UW + (size_t)(j0 + r) * UW + c];
            hr[r][c] = num;   // divide after sync
        }
        __syncthreads();
#pragma unroll
        for (int r = 0; r < 16; r++) hr[r][c] = hr[r][c] / den[r];
    }
    __syncthreads();

    float acc_d[16], acc_v[16];
    const float bad = b_ad[c], bav = b_av[c];
#pragma unroll
    for (int r = 0; r < 16; r++) { acc_d[r] = bad; acc_v[r] = bav; }
#pragma unroll 2
    for (int t = 0; t < DQ; t++) {
        float wd = W_ad[t * DQ + c];
        float wv = W_av[t * DQ + c];
#pragma unroll
        for (int r = 0; r < 16; r++) {
            acc_d[r] += hr[r][t] * wd;
            acc_v[r] += hr[r][t] * wv;
        }
    }

    const float wac = wa[c];
#pragma unroll
    for (int r = 0; r < 16; r++) prod[r][c] = acc_d[r] * wac;
    __syncthreads();

    const int warp = c >> 5, lane = c & 31;
#pragma unroll
    for (int rr = 0; rr < 4; rr++) {
        int r = warp * 4 + rr;
        float s = prod[r][lane] + prod[r][lane + 32] + prod[r][lane + 64] + prod[r][lane + 96];
#pragma unroll
        for (int o = 16; o > 0; o >>= 1) s += __shfl_xor_sync(0xffffffff, s, o);
        if (lane == 0) es_s[r] = __expf(s);
    }
    __syncthreads();

    if (W_dec == nullptr) {
#pragma unroll
        for (int r = 0; r < 16; r++)
            d_U[(size_t)(j0 + r) * UW + c] = __float2half(es_s[r] * acc_v[r]);
        if (c < 32) {
#pragma unroll
            for (int r = 0; r < 16; r++)
                d_U[(size_t)(j0 + r) * UW + 128 + c] = __float2half(c == 0 ? es_s[r] : 0.f);
        }
    } else {
        const float wdc = W_dec[c];
#pragma unroll
        for (int r = 0; r < 16; r++) prod[r][c] = acc_v[r] * wdc;
        __syncthreads();
#pragma unroll
        for (int rr = 0; rr < 4; rr++) {
            int r = warp * 4 + rr;
            float s = prod[r][lane] + prod[r][lane + 32] + prod[r][lane + 64] + prod[r][lane + 96];
#pragma unroll
            for (int o = 16; o > 0; o >>= 1) s += __shfl_xor_sync(0xffffffff, s, o);
            if (lane == 0) vdot[r] = s;
        }
        __syncthreads();
        if (c < 16) {
            d_uvec[j0 + c] = es_s[c] * vdot[c];
            d_evec[j0 + c] = es_s[c];
        }
    }
}

// ---------------- 4. split-K fp16 GEMM, 256 threads (8 warps), 3-stage cp.async ----------------
// part[s][i][n] = sum_{j in chunk s} E[j][i] * U[j][n]
// BM=64, BN=160, BK=32. Warps 4(M)x2(N): warp tile 16x80.
#define AS_STRIDE 72
#define BS_STRIDE 168

__global__ __launch_bounds__(256) void gemm_kernel()
{
    __shared__ __half As[3][32][AS_STRIDE];
    __shared__ __half Bs[3][32][BS_STRIDE];

    const int tid = threadIdx.x;
    const int m0 = blockIdx.x * 64;
    const size_t ks = (size_t)blockIdx.y * KCHUNK;
    const int warp = tid >> 5, lane = tid & 31;
    const int wm = (warp & 3) * 16, wn = (warp >> 2) * 80;

    float acc[10][4];
#pragma unroll
    for (int i = 0; i < 10; i++)
        acc[i][0] = acc[i][1] = acc[i][2] = acc[i][3] = 0.f;

    // cp.async indices: A 32x64 halfs = 256 chunks (1/thread); B 32x160 = 640 chunks (3/thread, some idle)
    const int ar0 = tid >> 3, ac0 = (tid & 7) * 8;
    int brow[3], bcol[3];
    bool bok[3];
#pragma unroll
    for (int i = 0; i < 3; i++) {
        int s = tid + 256 * i;
        bok[i] = s < 640;
        brow[i] = bok[i] ? s / 20 : 0;
        bcol[i] = bok[i] ? (s % 20) * 8 : 0;
    }

    const __half* Eg = d_E + ks * NN + m0;   // E[k][m]
    const __half* Ug = d_U + ks * UW;        // U[k][n]

#define ISSUE_STAGE(buf, kbase)                                                   \
    do {                                                                          \
        const __half* Ea = Eg + (size_t)(kbase) * NN;                             \
        const __half* Ua = Ug + (size_t)(kbase) * UW;                             \
        cp16(smem_u32(&As[buf][ar0][ac0]), Ea + (size_t)ar0 * NN + ac0);          \
        _Pragma("unroll")                                                         \
        for (int i = 0; i < 3; i++)                                               \
            if (bok[i])                                                           \
                cp16(smem_u32(&Bs[buf][brow[i]][bcol[i]]),                        \
                     Ua + (size_t)brow[i] * UW + bcol[i]);                        \
        asm volatile("cp.async.commit_group;");                                   \
    } while (0)

    ISSUE_STAGE(0, 0);
    ISSUE_STAGE(1, 32);
    ISSUE_STAGE(2, 64);

#pragma unroll 1
    for (int it = 0; it < KITERS; it++) {
        const int buf = it % 3;
        asm volatile("cp.async.wait_group 2;");
        __syncthreads();

#pragma unroll
        for (int kk = 0; kk < 2; kk++) {
            const int arow = kk * 16 + (lane & 7) + ((lane >> 4) << 3);
            const int acb = wm + ((lane >> 3) & 1) * 8;
            uint32_t a0[4];
            ldsm_x4t(a0[0], a0[1], a0[2], a0[3], smem_u32(&As[buf][arow][acb]));
#pragma unroll
            for (int nf = 0; nf < 5; nf++) {
                uint32_t b0, b1, b2, b3;
                ldsm_x4t(b0, b1, b2, b3,
                         smem_u32(&Bs[buf][kk * 16 + (lane & 15)][wn + nf * 16 + (lane >> 4) * 8]));
                float* c0 = acc[2 * nf];
                float* c1 = acc[2 * nf + 1];
                mma_f16(c0[0], c0[1], c0[2], c0[3], a0[0], a0[1], a0[2], a0[3], b0, b1);
                mma_f16(c1[0], c1[1], c1[2], c1[3], a0[0], a0[1], a0[2], a0[3], b2, b3);
            }
        }
        __syncthreads();
        if (it + 3 < KITERS) ISSUE_STAGE(buf, (it + 3) * 32);
    }

    const int g = lane >> 2, tg = lane & 3;
    float* P = d_part + ((size_t)blockIdx.y * NN + m0 + wm) * UW + wn;
#pragma unroll
    for (int nf = 0; nf < 10; nf++) {
        int col = nf * 8 + tg * 2;
        *(float2*)&P[(size_t)g * UW + col] = make_float2(acc[nf][0], acc[nf][1]);
        *(float2*)&P[(size_t)(g + 8) * UW + col] = make_float2(acc[nf][2], acc[nf][3]);
    }
#undef ISSUE_STAGE
}

// ---------------- 5. layer-3 GEMV: colsum of E weighted by u / e ----------------
#define JCH 64
#define NJC (NN / JCH)  // 64 chunks
__global__ __launch_bounds__(256) void gemv_kernel()
{
    float* gnum = d_part;                // [NJC][NN]
    float* gden = d_part + (size_t)NJC * NN;
    const int i0 = blockIdx.x * 1024;
    const int j0 = blockIdx.y * JCH;
    const int t = threadIdx.x;
    __shared__ float su[JCH], sev[JCH];
    if (t < JCH) { su[t] = d_uvec[j0 + t]; sev[t] = d_evec[j0 + t]; }
    __syncthreads();

    float n0 = 0.f, n1 = 0.f, n2 = 0.f, n3 = 0.f;
    float e0 = 0.f, e1 = 0.f, e2 = 0.f, e3 = 0.f;
    const __half* Eb = d_E + (size_t)j0 * NN + i0 + 2 * t;
#pragma unroll 4
    for (int j = 0; j < JCH; j++) {
        const float u = su[j], ev = sev[j];
        const __half2 a = *(const __half2*)(Eb + (size_t)j * NN);
        const __half2 b = *(const __half2*)(Eb + (size_t)j * NN + 512);
        const float2 af = __half22float2(a);
        const float2 bf = __half22float2(b);
        n0 += af.x * u;  n1 += af.y * u;
        n2 += bf.x * u;  n3 += bf.y * u;
        e0 += af.x * ev; e1 += af.y * ev;
        e2 += bf.x * ev; e3 += bf.y * ev;
    }
    const size_t base = (size_t)blockIdx.y * NN + i0 + 2 * t;
    *(float2*)&gnum[base] = make_float2(n0, n1);
    *(float2*)&gnum[base + 512] = make_float2(n2, n3);
    *(float2*)&gden[base] = make_float2(e0, e1);
    *(float2*)&gden[base + 512] = make_float2(e2, e3);
}

// ---------------- 6. finalize: out = num/den + b_dec (+mask) ----------------
__global__ __launch_bounds__(128) void finalize_kernel(
    const float* __restrict__ b_dec, const int* __restrict__ mask,
    float* __restrict__ out)
{
    const float* gnum = d_part;
    const float* gden = d_part + (size_t)NJC * NN;
    const int i = blockIdx.x * 128 + threadIdx.x;
    float num = 0.f, den = 0.f;
#pragma unroll 8
    for (int jc = 0; jc < NJC; jc++) {
        num += gnum[(size_t)jc * NN + i];
        den += gden[(size_t)jc * NN + i];
    }
    out[i] = (mask[i] == 0) ? __int_as_float(0xff800000)
                            : (num / den + b_dec[0]);
}

// ---------------- launch ----------------
extern "C" void kernel_launch(void* const* d_in, const int* in_sizes, int n_in,
                              void* d_out, int out_size)
{
    const float* x      = (const float*)d_in[0];
    const float* comms  = (const float*)d_in[1];
    const float* trans  = (const float*)d_in[2];
    const int*   mask   = (const int*)d_in[3];
    const float* W_enc  = (const float*)d_in[4];
    const float* b_enc  = (const float*)d_in[5];
    const float* W_ad   = (const float*)d_in[6];
    const float* b_ad   = (const float*)d_in[7];
    const float* w_att  = (const float*)d_in[8];
    // d_in[9] = b_att: cancels in row-softmax, unused
    const float* W_av   = (const float*)d_in[10];
    const float* b_av   = (const float*)d_in[11];
    const float* W_dec  = (const float*)d_in[12];
    const float* b_dec  = (const float*)d_in[13];
    float* out = (float*)d_out;

    encode_kernel<<<NN / 16, 128>>>(x, comms, W_enc, b_enc);
    buildE_kernel<<<(NN * (size_t)NN) / (256 * 8), 256>>>(trans);

    for (int k = 0; k < 3; k++) {
        computeU_kernel<<<NN / 16, 128>>>(W_ad + (size_t)k * DQ * DQ,
                                          b_ad + (size_t)k * DQ,
                                          w_att + (size_t)k * 2 * DQ,   // wa = first half
                                          W_av + (size_t)k * DQ * DQ,
                                          b_av + (size_t)k * DQ,
                                          k > 0,
                                          (k == 2) ? W_dec : nullptr);
        if (k < 2)
            gemm_kernel<<<dim3(NN / 64, SPLITK), 256>>>();
    }
    gemv_kernel<<<dim3(4, NJC), 256>>>();
    finalize_kernel<<<NN / 128, 128>>>(b_dec, mask, out);
}

// round 9
// speedup vs baseline: 1.5276x; 1.0192x over previous
#include <cuda_runtime.h>
#include <cuda_fp16.h>
#include <cstdint>

#define NN 4096
#define DQ 128
#define UW 160          // partial width: 128 v-cols + 1 denom col + pad
#define SPLITK 16
#define KCHUNK (NN / SPLITK)   // 256
#define KITERS (KCHUNK / 32)   // 8

// ---------------- scratch (static device globals; no allocation) ----------------
__device__ __half d_E[(size_t)NN * NN];                 // 32 MB: exp(trans) fp16, k-major
__device__ float  d_h[(size_t)NN * DQ];                 // encoder output (layer 0 input)
__device__ __half d_U[(size_t)NN * UW];                 // e^{sa}*v | e^{sa} | 0
__device__ __align__(16) __half d_part[(size_t)SPLITK * NN * UW];  // 21 MB fp16 split-K partials
__device__ float  d_uvec[NN];                           // layer3: e^{sa}*(v . W_dec)
__device__ float  d_evec[NN];                           // layer3: e^{sa}

// ---------------- PTX helpers ----------------
__device__ __forceinline__ uint32_t smem_u32(const void* p) {
    return (uint32_t)__cvta_generic_to_shared(p);
}
__device__ __forceinline__ void ldsm_x4t(uint32_t& r0, uint32_t& r1, uint32_t& r2, uint32_t& r3, uint32_t a) {
    asm volatile("ldmatrix.sync.aligned.m8n8.x4.trans.shared.b16 {%0,%1,%2,%3},[%4];"
                 : "=r"(r0), "=r"(r1), "=r"(r2), "=r"(r3) : "r"(a));
}
__device__ __forceinline__ void mma_f16(float& d0, float& d1, float& d2, float& d3,
                                        uint32_t a0, uint32_t a1, uint32_t a2, uint32_t a3,
                                        uint32_t b0, uint32_t b1) {
    asm volatile(
        "mma.sync.aligned.m16n8k16.row.col.f32.f16.f16.f32 "
        "{%0,%1,%2,%3},{%4,%5,%6,%7},{%8,%9},{%0,%1,%2,%3};"
        : "+f"(d0), "+f"(d1), "+f"(d2), "+f"(d3)
        : "r"(a0), "r"(a1), "r"(a2), "r"(a3), "r"(b0), "r"(b1));
}
__device__ __forceinline__ void cp16(uint32_t dst, const void* src) {
    asm volatile("cp.async.cg.shared.global [%0], [%1], 16;" :: "r"(dst), "l"(src));
}

// ---------------- 1. encode: h = [x|comms] @ W_enc + b_enc ----------------
__global__ __launch_bounds__(128) void encode_kernel(
    const float* __restrict__ x, const float* __restrict__ comms,
    const float* __restrict__ W_enc, const float* __restrict__ b_enc)
{
    const int i0 = blockIdx.x * 16;
    const int c = threadIdx.x;
    __shared__ float in[16][96];
    for (int idx = c; idx < 16 * 64; idx += 128) {
        int r = idx >> 6, t = idx & 63;
        in[r][t] = x[(size_t)(i0 + r) * 64 + t];
    }
    for (int idx = c; idx < 16 * 32; idx += 128) {
        int r = idx >> 5, t = idx & 31;
        in[r][64 + t] = comms[(size_t)(i0 + r) * 32 + t];
    }
    __syncthreads();
    float acc[16];
    const float be = b_enc[c];
#pragma unroll
    for (int r = 0; r < 16; r++) acc[r] = be;
#pragma unroll 4
    for (int t = 0; t < 96; t++) {
        float w = W_enc[t * DQ + c];
#pragma unroll
        for (int r = 0; r < 16; r++) acc[r] += in[r][t] * w;
    }
#pragma unroll
    for (int r = 0; r < 16; r++) d_h[(size_t)(i0 + r) * DQ + c] = acc[r];
}

// ---------------- 2. build E = exp(trans) elementwise (no transpose) ----------------
__global__ __launch_bounds__(256) void buildE_kernel(const float* __restrict__ trans)
{
    const size_t idx = ((size_t)blockIdx.x * 256 + threadIdx.x) * 8;
    float4 v0 = *(const float4*)(trans + idx);
    float4 v1 = *(const float4*)(trans + idx + 4);
    float e[8];
    e[0] = (v0.x == 0.f) ? 0.f : __expf(v0.x);
    e[1] = (v0.y == 0.f) ? 0.f : __expf(v0.y);
    e[2] = (v0.z == 0.f) ? 0.f : __expf(v0.z);
    e[3] = (v0.w == 0.f) ? 0.f : __expf(v0.w);
    e[4] = (v1.x == 0.f) ? 0.f : __expf(v1.x);
    e[5] = (v1.y == 0.f) ? 0.f : __expf(v1.y);
    e[6] = (v1.z == 0.f) ? 0.f : __expf(v1.z);
    e[7] = (v1.w == 0.f) ? 0.f : __expf(v1.w);
    __half2 h2[4];
#pragma unroll
    for (int i = 0; i < 4; i++)
        h2[i] = __floats2half2_rn(e[2 * i], e[2 * i + 1]);
    *(uint4*)(d_E + idx) = *(uint4*)h2;
}

// ---------------- 3. per-layer U (fp16); fused dual-weight pass ----------------
__global__ __launch_bounds__(128) void computeU_kernel(
    const float* __restrict__ W_ad, const float* __restrict__ b_ad,
    const float* __restrict__ wa,   const float* __restrict__ W_av,
    const float* __restrict__ b_av, int use_part,
    const float* __restrict__ W_dec)
{
    const int j0 = blockIdx.x * 16;
    const int c = threadIdx.x;
    __shared__ float hr[16][DQ];
    __shared__ float prod[16][DQ + 1];
    __shared__ float es_s[16];
    __shared__ float den[16];
    __shared__ float vdot[16];

    if (!use_part) {
#pragma unroll
        for (int r = 0; r < 16; r++) hr[r][c] = d_h[(size_t)(j0 + r) * DQ + c];
    } else {
        if (c < 16) {
            float d = 0.f;
#pragma unroll
            for (int s = 0; s < SPLITK; s++)
                d += __half2float(d_part[((size_t)s * NN + j0 + c) * UW + 128]);
            den[c] = d;
        }
#pragma unroll
        for (int r = 0; r < 16; r++) {
            float num = 0.f;
#pragma unroll
            for (int s = 0; s < SPLITK; s++)
                num += __half2float(d_part[((size_t)s * NN + j0 + r) * UW + c]);
            hr[r][c] = num;   // divide after sync
        }
        __syncthreads();
#pragma unroll
        for (int r = 0; r < 16; r++) hr[r][c] = hr[r][c] / den[r];
    }
    __syncthreads();

    float acc_d[16], acc_v[16];
    const float bad = b_ad[c], bav = b_av[c];
#pragma unroll
    for (int r = 0; r < 16; r++) { acc_d[r] = bad; acc_v[r] = bav; }
#pragma unroll 2
    for (int t = 0; t < DQ; t++) {
        float wd = W_ad[t * DQ + c];
        float wv = W_av[t * DQ + c];
#pragma unroll
        for (int r = 0; r < 16; r++) {
            acc_d[r] += hr[r][t] * wd;
            acc_v[r] += hr[r][t] * wv;
        }
    }

    const float wac = wa[c];
#pragma unroll
    for (int r = 0; r < 16; r++) prod[r][c] = acc_d[r] * wac;
    __syncthreads();

    const int warp = c >> 5, lane = c & 31;
#pragma unroll
    for (int rr = 0; rr < 4; rr++) {
        int r = warp * 4 + rr;
        float s = prod[r][lane] + prod[r][lane + 32] + prod[r][lane + 64] + prod[r][lane + 96];
#pragma unroll
        for (int o = 16; o > 0; o >>= 1) s += __shfl_xor_sync(0xffffffff, s, o);
        if (lane == 0) es_s[r] = __expf(s);
    }
    __syncthreads();

    if (W_dec == nullptr) {
#pragma unroll
        for (int r = 0; r < 16; r++)
            d_U[(size_t)(j0 + r) * UW + c] = __float2half(es_s[r] * acc_v[r]);
        if (c < 32) {
#pragma unroll
            for (int r = 0; r < 16; r++)
                d_U[(size_t)(j0 + r) * UW + 128 + c] = __float2half(c == 0 ? es_s[r] : 0.f);
        }
    } else {
        const float wdc = W_dec[c];
#pragma unroll
        for (int r = 0; r < 16; r++) prod[r][c] = acc_v[r] * wdc;
        __syncthreads();
#pragma unroll
        for (int rr = 0; rr < 4; rr++) {
            int r = warp * 4 + rr;
            float s = prod[r][lane] + prod[r][lane + 32] + prod[r][lane + 64] + prod[r][lane + 96];
#pragma unroll
            for (int o = 16; o > 0; o >>= 1) s += __shfl_xor_sync(0xffffffff, s, o);
            if (lane == 0) vdot[r] = s;
        }
        __syncthreads();
        if (c < 16) {
            d_uvec[j0 + c] = es_s[c] * vdot[c];
            d_evec[j0 + c] = es_s[c];
        }
    }
}

// ---------------- 4. split-K fp16 GEMM: BM=128, 8 warps (4M x 2N), warp tile 32x80 ----------------
// part[s][i][n] = sum_{j in chunk s} E[j][i] * U[j][n]; 2-stage cp.async; fp16 partials
#define AS_STRIDE 136   // 128 + 8 pad: conflict-free trans ldsm
#define BS_STRIDE 168   // 160 + 8 pad

__global__ __launch_bounds__(256) void gemm_kernel()
{
    __shared__ __half As[2][32][AS_STRIDE];   // [k][m]
    __shared__ __half Bs[2][32][BS_STRIDE];   // [k][n]

    const int tid = threadIdx.x;
    const int m0 = blockIdx.x * 128;
    const size_t ks = (size_t)blockIdx.y * KCHUNK;
    const int warp = tid >> 5, lane = tid & 31;
    const int wm = (warp & 3) * 32, wn = (warp >> 2) * 80;

    float acc[2][10][4];
#pragma unroll
    for (int mi = 0; mi < 2; mi++)
#pragma unroll
        for (int i = 0; i < 10; i++)
            acc[mi][i][0] = acc[mi][i][1] = acc[mi][i][2] = acc[mi][i][3] = 0.f;

    // cp.async: A 32x128 halfs = 512 16B-chunks (2/thread); B 32x160 = 640 chunks (3/thread masked)
    const int ar0 = tid >> 4,          ac0 = (tid & 15) * 8;
    const int ar1 = (tid + 256) >> 4,  ac1 = ((tid + 256) & 15) * 8;
    int brow[3], bcol[3];
    bool bok[3];
#pragma unroll
    for (int i = 0; i < 3; i++) {
        int s = tid + 256 * i;
        bok[i] = s < 640;
        brow[i] = bok[i] ? s / 20 : 0;
        bcol[i] = bok[i] ? (s % 20) * 8 : 0;
    }

    const __half* Eg = d_E + ks * NN + m0;   // E[k][m]
    const __half* Ug = d_U + ks * UW;        // U[k][n]

#define ISSUE_STAGE(buf, kbase)                                                   \
    do {                                                                          \
        const __half* Ea = Eg + (size_t)(kbase) * NN;                             \
        const __half* Ua = Ug + (size_t)(kbase) * UW;                             \
        cp16(smem_u32(&As[buf][ar0][ac0]), Ea + (size_t)ar0 * NN + ac0);          \
        cp16(smem_u32(&As[buf][ar1][ac1]), Ea + (size_t)ar1 * NN + ac1);          \
        _Pragma("unroll")                                                         \
        for (int i = 0; i < 3; i++)                                               \
            if (bok[i])                                                           \
                cp16(smem_u32(&Bs[buf][brow[i]][bcol[i]]),                        \
                     Ua + (size_t)brow[i] * UW + bcol[i]);                        \
        asm volatile("cp.async.commit_group;");                                   \
    } while (0)

    ISSUE_STAGE(0, 0);
    ISSUE_STAGE(1, 32);

#pragma unroll 1
    for (int it = 0; it < KITERS; it++) {
        const int buf = it & 1;
        if (it == KITERS - 1) asm volatile("cp.async.wait_group 0;");
        else                  asm volatile("cp.async.wait_group 1;");
        __syncthreads();

#pragma unroll
        for (int kk = 0; kk < 2; kk++) {
            const int arow = kk * 16 + (lane & 7) + ((lane >> 4) << 3);
            const int acb = wm + ((lane >> 3) & 1) * 8;
            uint32_t a0[4], a1[4];
            ldsm_x4t(a0[0], a0[1], a0[2], a0[3], smem_u32(&As[buf][arow][acb]));
            ldsm_x4t(a1[0], a1[1], a1[2], a1[3], smem_u32(&As[buf][arow][acb + 16]));
#pragma unroll
            for (int nf = 0; nf < 5; nf++) {
                uint32_t b0, b1, b2, b3;
                ldsm_x4t(b0, b1, b2, b3,
                         smem_u32(&Bs[buf][kk * 16 + (lane & 15)][wn + nf * 16 + (lane >> 4) * 8]));
                float* c00 = acc[0][2 * nf];
                float* c01 = acc[0][2 * nf + 1];
                float* c10 = acc[1][2 * nf];
                float* c11 = acc[1][2 * nf + 1];
                mma_f16(c00[0], c00[1], c00[2], c00[3], a0[0], a0[1], a0[2], a0[3], b0, b1);
                mma_f16(c01[0], c01[1], c01[2], c01[3], a0[0], a0[1], a0[2], a0[3], b2, b3);
                mma_f16(c10[0], c10[1], c10[2], c10[3], a1[0], a1[1], a1[2], a1[3], b0, b1);
                mma_f16(c11[0], c11[1], c11[2], c11[3], a1[0], a1[1], a1[2], a1[3], b2, b3);
            }
        }
        __syncthreads();
        if (it + 2 < KITERS) ISSUE_STAGE(buf, (it + 2) * 32);
    }

    // epilogue: fp16 split partials (no atomics -> deterministic)
    const int g = lane >> 2, tg = lane & 3;
    __half* P = d_part + ((size_t)blockIdx.y * NN + m0 + wm) * UW + wn;
#pragma unroll
    for (int mi = 0; mi < 2; mi++) {
#pragma unroll
        for (int nf = 0; nf < 10; nf++) {
            int col = nf * 8 + tg * 2;
            int r0 = mi * 16 + g;
            *(__half2*)&P[(size_t)r0 * UW + col] =
                __floats2half2_rn(acc[mi][nf][0], acc[mi][nf][1]);
            *(__half2*)&P[(size_t)(r0 + 8) * UW + col] =
                __floats2half2_rn(acc[mi][nf][2], acc[mi][nf][3]);
        }
    }
#undef ISSUE_STAGE
}

// ---------------- 5. layer-3 GEMV: colsum of E weighted by u / e ----------------
// scratch planes (fp32) live in d_part storage (free after layer-2 computeU)
#define JCH 64
#define NJC (NN / JCH)  // 64 chunks
__global__ __launch_bounds__(256) void gemv_kernel()
{
    float* gnum = reinterpret_cast<float*>(d_part);      // [NJC][NN]
    float* gden = gnum + (size_t)NJC * NN;
    const int i0 = blockIdx.x * 1024;
    const int j0 = blockIdx.y * JCH;
    const int t = threadIdx.x;
    __shared__ float su[JCH], sev[JCH];
    if (t < JCH) { su[t] = d_uvec[j0 + t]; sev[t] = d_evec[j0 + t]; }
    __syncthreads();

    float n0 = 0.f, n1 = 0.f, n2 = 0.f, n3 = 0.f;
    float e0 = 0.f, e1 = 0.f, e2 = 0.f, e3 = 0.f;
    const __half* Eb = d_E + (size_t)j0 * NN + i0 + 2 * t;
#pragma unroll 4
    for (int j = 0; j < JCH; j++) {
        const float u = su[j], ev = sev[j];
        const __half2 a = *(const __half2*)(Eb + (size_t)j * NN);
        const __half2 b = *(const __half2*)(Eb + (size_t)j * NN + 512);
        const float2 af = __half22float2(a);
        const float2 bf = __half22float2(b);
        n0 += af.x * u;  n1 += af.y * u;
        n2 += bf.x * u;  n3 += bf.y * u;
        e0 += af.x * ev; e1 += af.y * ev;
        e2 += bf.x * ev; e3 += bf.y * ev;
    }
    const size_t base = (size_t)blockIdx.y * NN + i0 + 2 * t;
    *(float2*)&gnum[base] = make_float2(n0, n1);
    *(float2*)&gnum[base + 512] = make_float2(n2, n3);
    *(float2*)&gden[base] = make_float2(e0, e1);
    *(float2*)&gden[base + 512] = make_float2(e2, e3);
}

// ---------------- 6. finalize: out = num/den + b_dec (+mask) ----------------
__global__ __launch_bounds__(128) void finalize_kernel(
    const float* __restrict__ b_dec, const int* __restrict__ mask,
    float* __restrict__ out)
{
    const float* gnum = reinterpret_cast<const float*>(d_part);
    const float* gden = gnum + (size_t)NJC * NN;
    const int i = blockIdx.x * 128 + threadIdx.x;
    float num = 0.f, den = 0.f;
#pragma unroll 8
    for (int jc = 0; jc < NJC; jc++) {
        num += gnum[(size_t)jc * NN + i];
        den += gden[(size_t)jc * NN + i];
    }
    out[i] = (mask[i] == 0) ? __int_as_float(0xff800000)
                            : (num / den + b_dec[0]);
}

// ---------------- launch ----------------
extern "C" void kernel_launch(void* const* d_in, const int* in_sizes, int n_in,
                              void* d_out, int out_size)
{
    const float* x      = (const float*)d_in[0];
    const float* comms  = (const float*)d_in[1];
    const float* trans  = (const float*)d_in[2];
    const int*   mask   = (const int*)d_in[3];
    const float* W_enc  = (const float*)d_in[4];
    const float* b_enc  = (const float*)d_in[5];
    const float* W_ad   = (const float*)d_in[6];
    const float* b_ad   = (const float*)d_in[7];
    const float* w_att  = (const float*)d_in[8];
    // d_in[9] = b_att: cancels in row-softmax, unused
    const float* W_av   = (const float*)d_in[10];
    const float* b_av   = (const float*)d_in[11];
    const float* W_dec  = (const float*)d_in[12];
    const float* b_dec  = (const float*)d_in[13];
    float* out = (float*)d_out;

    encode_kernel<<<NN / 16, 128>>>(x, comms, W_enc, b_enc);
    buildE_kernel<<<(NN * (size_t)NN) / (256 * 8), 256>>>(trans);

    for (int k = 0; k < 3; k++) {
        computeU_kernel<<<NN / 16, 128>>>(W_ad + (size_t)k * DQ * DQ,
                                          b_ad + (size_t)k * DQ,
                                          w_att + (size_t)k * 2 * DQ,   // wa = first half
                                          W_av + (size_t)k * DQ * DQ,
                                          b_av + (size_t)k * DQ,
                                          k > 0,
                                          (k == 2) ? W_dec : nullptr);
        if (k < 2)
            gemm_kernel<<<dim3(NN / 128, SPLITK), 256>>>();
    }
    gemv_kernel<<<dim3(4, NJC), 256>>>();
    finalize_kernel<<<NN / 128, 128>>>(b_dec, mask, out);
}

// round 11
// speedup vs baseline: 1.8023x; 1.1798x over previous
#include <cuda_runtime.h>
#include <cuda_fp16.h>
#include <cstdint>

#define NN 4096
#define DQ 128
#define PW 128          // partial/U width: exactly 128 v-cols (den separate)
#define SPLITK 16
#define KCHUNK (NN / SPLITK)   // 256
#define KITERS (KCHUNK / 32)   // 8

// ---------------- scratch (static device globals; no allocation) ----------------
__device__ __half d_E[(size_t)NN * NN];                 // 32 MB: exp(trans) fp16, k-major
__device__ float  d_h[(size_t)NN * DQ];                 // encoder output (layer 0 input)
__device__ __half d_U[(size_t)NN * PW];                 // e^{sa}*v
__device__ __align__(16) __half d_part[(size_t)SPLITK * NN * PW];  // 16.8 MB fp16 split-K partials
__device__ float  d_denp[(size_t)SPLITK * NN];          // fp32 den partials
__device__ float  d_uvec[NN];                           // layer3: e^{sa}*(v . W_dec)
__device__ float  d_evec[NN];                           // per-layer e^{sa} (gemm den; layer3 gemv)

// ---------------- PTX helpers ----------------
__device__ __forceinline__ uint32_t smem_u32(const void* p) {
    return (uint32_t)__cvta_generic_to_shared(p);
}
__device__ __forceinline__ void ldsm_x4t(uint32_t& r0, uint32_t& r1, uint32_t& r2, uint32_t& r3, uint32_t a) {
    asm volatile("ldmatrix.sync.aligned.m8n8.x4.trans.shared.b16 {%0,%1,%2,%3},[%4];"
                 : "=r"(r0), "=r"(r1), "=r"(r2), "=r"(r3) : "r"(a));
}
__device__ __forceinline__ void mma_f16(float& d0, float& d1, float& d2, float& d3,
                                        uint32_t a0, uint32_t a1, uint32_t a2, uint32_t a3,
                                        uint32_t b0, uint32_t b1) {
    asm volatile(
        "mma.sync.aligned.m16n8k16.row.col.f32.f16.f16.f32 "
        "{%0,%1,%2,%3},{%4,%5,%6,%7},{%8,%9},{%0,%1,%2,%3};"
        : "+f"(d0), "+f"(d1), "+f"(d2), "+f"(d3)
        : "r"(a0), "r"(a1), "r"(a2), "r"(a3), "r"(b0), "r"(b1));
}
__device__ __forceinline__ void cp16(uint32_t dst, const void* src) {
    asm volatile("cp.async.cg.shared.global [%0], [%1], 16;" :: "r"(dst), "l"(src));
}

// ---------------- 1. encode: h = [x|comms] @ W_enc + b_enc ----------------
__global__ __launch_bounds__(128) void encode_kernel(
    const float* __restrict__ x, const float* __restrict__ comms,
    const float* __restrict__ W_enc, const float* __restrict__ b_enc)
{
    const int i0 = blockIdx.x * 16;
    const int c = threadIdx.x;
    __shared__ float in[16][96];
    for (int idx = c; idx < 16 * 64; idx += 128) {
        int r = idx >> 6, t = idx & 63;
        in[r][t] = x[(size_t)(i0 + r) * 64 + t];
    }
    for (int idx = c; idx < 16 * 32; idx += 128) {
        int r = idx >> 5, t = idx & 31;
        in[r][64 + t] = comms[(size_t)(i0 + r) * 32 + t];
    }
    __syncthreads();
    float acc[16];
    const float be = b_enc[c];
#pragma unroll
    for (int r = 0; r < 16; r++) acc[r] = be;
#pragma unroll 4
    for (int t = 0; t < 96; t++) {
        float w = W_enc[t * DQ + c];
#pragma unroll
        for (int r = 0; r < 16; r++) acc[r] += in[r][t] * w;
    }
#pragma unroll
    for (int r = 0; r < 16; r++) d_h[(size_t)(i0 + r) * DQ + c] = acc[r];
}

// ---------------- 2. build E = exp(trans) elementwise ----------------
__global__ __launch_bounds__(256) void buildE_kernel(const float* __restrict__ trans)
{
    const size_t idx = ((size_t)blockIdx.x * 256 + threadIdx.x) * 8;
    float4 v0 = *(const float4*)(trans + idx);
    float4 v1 = *(const float4*)(trans + idx + 4);
    float e[8];
    e[0] = (v0.x == 0.f) ? 0.f : __expf(v0.x);
    e[1] = (v0.y == 0.f) ? 0.f : __expf(v0.y);
    e[2] = (v0.z == 0.f) ? 0.f : __expf(v0.z);
    e[3] = (v0.w == 0.f) ? 0.f : __expf(v0.w);
    e[4] = (v1.x == 0.f) ? 0.f : __expf(v1.x);
    e[5] = (v1.y == 0.f) ? 0.f : __expf(v1.y);
    e[6] = (v1.z == 0.f) ? 0.f : __expf(v1.z);
    e[7] = (v1.w == 0.f) ? 0.f : __expf(v1.w);
    __half2 h2[4];
#pragma unroll
    for (int i = 0; i < 4; i++)
        h2[i] = __floats2half2_rn(e[2 * i], e[2 * i + 1]);
    *(uint4*)(d_E + idx) = *(uint4*)h2;
}

// ---------------- 3. per-layer U; warp-split dual-weight pass (256 thr) ----------------
// grp0 (warps 0-3): W_ad path -> es_s, d_evec. grp1 (warps 4-7): W_av path -> d_U.
__global__ __launch_bounds__(256) void computeU_kernel(
    const float* __restrict__ W_ad, const float* __restrict__ b_ad,
    const float* __restrict__ wa,   const float* __restrict__ W_av,
    const float* __restrict__ b_av, int use_part,
    const float* __restrict__ W_dec)
{
    const int j0 = blockIdx.x * 16;
    const int tid = threadIdx.x;
    const int grp = tid >> 7;         // 0: att/d path, 1: v path
    const int c = tid & 127;
    __shared__ float hr[16][DQ];
    __shared__ float prod[16][DQ + 1];
    __shared__ float es_s[16];
    __shared__ float den[16];
    __shared__ float vdot[16];

    if (!use_part) {
#pragma unroll
        for (int r8 = 0; r8 < 8; r8++) {
            int r = grp * 8 + r8;
            hr[r][c] = d_h[(size_t)(j0 + r) * DQ + c];
        }
        __syncthreads();
    } else {
        if (grp == 0 && c < 16) {
            float d = 0.f;
#pragma unroll
            for (int s = 0; s < SPLITK; s++)
                d += d_denp[(size_t)s * NN + j0 + c];
            den[c] = d;
        }
#pragma unroll
        for (int r8 = 0; r8 < 8; r8++) {
            int r = grp * 8 + r8;
            float num = 0.f;
#pragma unroll
            for (int s = 0; s < SPLITK; s++)
                num += __half2float(d_part[((size_t)s * NN + j0 + r) * PW + c]);
            hr[r][c] = num;
        }
        __syncthreads();
#pragma unroll
        for (int r8 = 0; r8 < 8; r8++) {
            int r = grp * 8 + r8;
            hr[r][c] = hr[r][c] / den[r];
        }
        __syncthreads();
    }

    const float* W = grp ? W_av : W_ad;
    const float bb = grp ? b_av[c] : b_ad[c];
    float acc[16];
#pragma unroll
    for (int r = 0; r < 16; r++) acc[r] = bb;
#pragma unroll 4
    for (int t = 0; t < DQ; t++) {
        float w = W[t * DQ + c];
#pragma unroll
        for (int r = 0; r < 16; r++) acc[r] += hr[r][t] * w;
    }

    if (grp == 0) {
        const float wac = wa[c];
#pragma unroll
        for (int r = 0; r < 16; r++) prod[r][c] = acc[r] * wac;
    }
    __syncthreads();

    const int warp = tid >> 5, lane = tid & 31;
    if (grp == 0) {
#pragma unroll
        for (int rr = 0; rr < 4; rr++) {
            int r = warp * 4 + rr;
            float s = prod[r][lane] + prod[r][lane + 32] + prod[r][lane + 64] + prod[r][lane + 96];
#pragma unroll
            for (int o = 16; o > 0; o >>= 1) s += __shfl_xor_sync(0xffffffff, s, o);
            if (lane == 0) es_s[r] = __expf(s);
        }
    }
    __syncthreads();

    if (W_dec == nullptr) {
        if (grp == 1) {
#pragma unroll
            for (int r = 0; r < 16; r++)
                d_U[(size_t)(j0 + r) * PW + c] = __float2half(es_s[r] * acc[r]);
        } else if (c < 16) {
            d_evec[j0 + c] = es_s[c];
        }
    } else {
        if (grp == 1) {
            const float wdc = W_dec[c];
#pragma unroll
            for (int r = 0; r < 16; r++) prod[r][c] = acc[r] * wdc;
        }
        __syncthreads();
        if (grp == 1) {
#pragma unroll
            for (int rr = 0; rr < 4; rr++) {
                int r = (warp - 4) * 4 + rr;
                float s = prod[r][lane] + prod[r][lane + 32] + prod[r][lane + 64] + prod[r][lane + 96];
#pragma unroll
                for (int o = 16; o > 0; o >>= 1) s += __shfl_xor_sync(0xffffffff, s, o);
                if (lane == 0) vdot[r] = s;
            }
        }
        __syncthreads();
        if (grp == 0 && c < 16) {
            d_uvec[j0 + c] = es_s[c] * vdot[c];
            d_evec[j0 + c] = es_s[c];
        }
    }
}

// ---------------- 4. split-K fp16 GEMM: BM=128, BN=128, fused den reduction ----------------
// part[s][i][n] = sum_{j in chunk s} E[j][i]*U[j][n];  denp[s][i] = sum_j E[j][i]*e[j]
// 8 warps (4M x 2N), warp tile 32x64. 4-buffer / 3-deep cp.async, single sync per iter.
#define AST 136                            // 128 + 8 pad halfs
#define ABUF 4352                          // 32*136 halfs per buffer
#define SE_OFF (8 * ABUF)                  // floats after 8 half-buffers
#define GEMM_SMEM (8 * ABUF * 2 + (128 + 256) * 4)

__global__ __launch_bounds__(256) void gemm_kernel()
{
    extern __shared__ __half sm[];
    float* se = (float*)(sm + SE_OFF);          // [4][32]
    float* sden = se + 128;                     // [2][128]

    const int tid = threadIdx.x;
    const int m0 = blockIdx.x * 128;
    const size_t ks = (size_t)blockIdx.y * KCHUNK;
    const int warp = tid >> 5, lane = tid & 31;
    const int wm = (warp & 3) * 32, wn = (warp >> 2) * 64;

    float acc[2][8][4];
#pragma unroll
    for (int mi = 0; mi < 2; mi++)
#pragma unroll
        for (int i = 0; i < 8; i++)
            acc[mi][i][0] = acc[mi][i][1] = acc[mi][i][2] = acc[mi][i][3] = 0.f;
    float den = 0.f;

    // cp.async: each tile 32 rows x 128 halfs = 512 16B-chunks, 2/thread
    const int r0 = tid >> 4, cc0 = (tid & 15) * 8;
    const int r1 = 16 + r0;
    const __half* Eg = d_E + ks * NN + m0;   // E[k][m]
    const __half* Ug = d_U + ks * PW;        // U[k][n]
    const float* ev = d_evec + ks;

#define ISSUE_STAGE(buf, kb)                                                      \
    do {                                                                          \
        const __half* Ea = Eg + (size_t)(kb) * NN;                                \
        const __half* Ua = Ug + (size_t)(kb) * PW;                                \
        cp16(smem_u32(&sm[(buf) * ABUF + r0 * AST + cc0]), Ea + (size_t)r0 * NN + cc0); \
        cp16(smem_u32(&sm[(buf) * ABUF + r1 * AST + cc0]), Ea + (size_t)r1 * NN + cc0); \
        cp16(smem_u32(&sm[(4 + (buf)) * ABUF + r0 * AST + cc0]), Ua + (size_t)r0 * PW + cc0); \
        cp16(smem_u32(&sm[(4 + (buf)) * ABUF + r1 * AST + cc0]), Ua + (size_t)r1 * PW + cc0); \
        if (tid >= 224) se[(buf) * 32 + tid - 224] = ev[(kb) + tid - 224];        \
        asm volatile("cp.async.commit_group;");                                   \
    } while (0)

    ISSUE_STAGE(0, 0);
    ISSUE_STAGE(1, 32);
    ISSUE_STAGE(2, 64);

    const int dm = tid & 127, kh = (tid >> 7) << 4;

#pragma unroll 1
    for (int it = 0; it < KITERS; it++) {
        const int buf = it & 3;
        if (it < KITERS - 2)       asm volatile("cp.async.wait_group 2;" ::: "memory");
        else if (it == KITERS - 2) asm volatile("cp.async.wait_group 1;" ::: "memory");
        else                       asm volatile("cp.async.wait_group 0;" ::: "memory");
        __syncthreads();

        // fused den: den[m] += sum_k E[k][m]*e[k] (each thread: 16 k's for its m)
#pragma unroll
        for (int k2 = 0; k2 < 16; k2++)
            den += __half2float(sm[buf * ABUF + (kh + k2) * AST + dm]) * se[buf * 32 + kh + k2];

#pragma unroll
        for (int kk = 0; kk < 2; kk++) {
            const int arow = kk * 16 + (lane & 7) + ((lane >> 4) << 3);
            const int acb = wm + ((lane >> 3) & 1) * 8;
            uint32_t a0[4], a1[4];
            ldsm_x4t(a0[0], a0[1], a0[2], a0[3],
                     smem_u32(&sm[buf * ABUF + arow * AST + acb]));
            ldsm_x4t(a1[0], a1[1], a1[2], a1[3],
                     smem_u32(&sm[buf * ABUF + arow * AST + acb + 16]));
#pragma unroll
            for (int nf = 0; nf < 4; nf++) {
                uint32_t b0, b1, b2, b3;
                ldsm_x4t(b0, b1, b2, b3,
                         smem_u32(&sm[(4 + buf) * ABUF + (kk * 16 + (lane & 15)) * AST
                                      + wn + nf * 16 + (lane >> 4) * 8]));
                float* c00 = acc[0][2 * nf];
                float* c01 = acc[0][2 * nf + 1];
                float* c10 = acc[1][2 * nf];
                float* c11 = acc[1][2 * nf + 1];
                mma_f16(c00[0], c00[1], c00[2], c00[3], a0[0], a0[1], a0[2], a0[3], b0, b1);
                mma_f16(c01[0], c01[1], c01[2], c01[3], a0[0], a0[1], a0[2], a0[3], b2, b3);
                mma_f16(c10[0], c10[1], c10[2], c10[3], a1[0], a1[1], a1[2], a1[3], b0, b1);
                mma_f16(c11[0], c11[1], c11[2], c11[3], a1[0], a1[1], a1[2], a1[3], b2, b3);
            }
        }
        // issue stage it+3 into buf (it+3)&3 — last used at iter it-1, all warps past sync(it)
        if (it + 3 < KITERS) ISSUE_STAGE((it + 3) & 3, (it + 3) * 32);
    }

    // epilogue: fp16 split partials + fp32 den partial
    const int g = lane >> 2, tg = lane & 3;
    __half* P = d_part + ((size_t)blockIdx.y * NN + m0 + wm) * PW + wn;
#pragma unroll
    for (int mi = 0; mi < 2; mi++) {
#pragma unroll
        for (int fi = 0; fi < 8; fi++) {
            int col = fi * 8 + tg * 2;
            int rr0 = mi * 16 + g;
            *(__half2*)&P[(size_t)rr0 * PW + col] =
                __floats2half2_rn(acc[mi][fi][0], acc[mi][fi][1]);
            *(__half2*)&P[(size_t)(rr0 + 8) * PW + col] =
                __floats2half2_rn(acc[mi][fi][2], acc[mi][fi][3]);
        }
    }
    sden[(tid >> 7) * 128 + dm] = den;
    __syncthreads();
    if (tid < 128)
        d_denp[(size_t)blockIdx.y * NN + m0 + tid] = sden[tid] + sden[128 + tid];
#undef ISSUE_STAGE
}

// ---------------- 5. layer-3 GEMV: colsum of E weighted by u / e ----------------
#define JCH 64
#define NJC (NN / JCH)  // 64 chunks
__global__ __launch_bounds__(256) void gemv_kernel()
{
    float* gnum = reinterpret_cast<float*>(d_part);      // [NJC][NN] scratch
    float* gden = gnum + (size_t)NJC * NN;
    const int i0 = blockIdx.x * 1024;
    const int j0 = blockIdx.y * JCH;
    const int t = threadIdx.x;
    __shared__ float su[JCH], sev[JCH];
    if (t < JCH) { su[t] = d_uvec[j0 + t]; sev[t] = d_evec[j0 + t]; }
    __syncthreads();

    float n0 = 0.f, n1 = 0.f, n2 = 0.f, n3 = 0.f;
    float e0 = 0.f, e1 = 0.f, e2 = 0.f, e3 = 0.f;
    const __half* Eb = d_E + (size_t)j0 * NN + i0 + 2 * t;
#pragma unroll 4
    for (int j = 0; j < JCH; j++) {
        const float u = su[j], evv = sev[j];
        const __half2 a = *(const __half2*)(Eb + (size_t)j * NN);
        const __half2 b = *(const __half2*)(Eb + (size_t)j * NN + 512);
        const float2 af = __half22float2(a);
        const float2 bf = __half22float2(b);
        n0 += af.x * u;   n1 += af.y * u;
        n2 += bf.x * u;   n3 += bf.y * u;
        e0 += af.x * evv; e1 += af.y * evv;
        e2 += bf.x * evv; e3 += bf.y * evv;
    }
    const size_t base = (size_t)blockIdx.y * NN + i0 + 2 * t;
    *(float2*)&gnum[base] = make_float2(n0, n1);
    *(float2*)&gnum[base + 512] = make_float2(n2, n3);
    *(float2*)&gden[base] = make_float2(e0, e1);
    *(float2*)&gden[base + 512] = make_float2(e2, e3);
}

// ---------------- 6. finalize: out = num/den + b_dec (+mask) ----------------
__global__ __launch_bounds__(128) void finalize_kernel(
    const float* __restrict__ b_dec, const int* __restrict__ mask,
    float* __restrict__ out)
{
    const float* gnum = reinterpret_cast<const float*>(d_part);
    const float* gden = gnum + (size_t)NJC * NN;
    const int i = blockIdx.x * 128 + threadIdx.x;
    float num = 0.f, den = 0.f;
#pragma unroll 8
    for (int jc = 0; jc < NJC; jc++) {
        num += gnum[(size_t)jc * NN + i];
        den += gden[(size_t)jc * NN + i];
    }
    out[i] = (mask[i] == 0) ? __int_as_float(0xff800000)
                            : (num / den + b_dec[0]);
}

// ---------------- launch ----------------
extern "C" void kernel_launch(void* const* d_in, const int* in_sizes, int n_in,
                              void* d_out, int out_size)
{
    const float* x      = (const float*)d_in[0];
    const float* comms  = (const float*)d_in[1];
    const float* trans  = (const float*)d_in[2];
    const int*   mask   = (const int*)d_in[3];
    const float* W_enc  = (const float*)d_in[4];
    const float* b_enc  = (const float*)d_in[5];
    const float* W_ad   = (const float*)d_in[6];
    const float* b_ad   = (const float*)d_in[7];
    const float* w_att  = (const float*)d_in[8];
    // d_in[9] = b_att: cancels in row-softmax, unused
    const float* W_av   = (const float*)d_in[10];
    const float* b_av   = (const float*)d_in[11];
    const float* W_dec  = (const float*)d_in[12];
    const float* b_dec  = (const float*)d_in[13];
    float* out = (float*)d_out;

    cudaFuncSetAttribute(gemm_kernel, cudaFuncAttributeMaxDynamicSharedMemorySize,
                         GEMM_SMEM);

    encode_kernel<<<NN / 16, 128>>>(x, comms, W_enc, b_enc);
    buildE_kernel<<<(NN * (size_t)NN) / (256 * 8), 256>>>(trans);

    for (int k = 0; k < 3; k++) {
        computeU_kernel<<<NN / 16, 256>>>(W_ad + (size_t)k * DQ * DQ,
                                          b_ad + (size_t)k * DQ,
                                          w_att + (size_t)k * 2 * DQ,   // wa = first half
                                          W_av + (size_t)k * DQ * DQ,
                                          b_av + (size_t)k * DQ,
                                          k > 0,
                                          (k == 2) ? W_dec : nullptr);
        if (k < 2)
            gemm_kernel<<<dim3(NN / 128, SPLITK), 256, GEMM_SMEM>>>();
    }
    gemv_kernel<<<dim3(4, NJC), 256>>>();
    finalize_kernel<<<NN / 128, 128>>>(b_dec, mask, out);
}

// round 12
// speedup vs baseline: 1.8684x; 1.0367x over previous
#include <cuda_runtime.h>
#include <cuda_fp16.h>
#include <cstdint>

#define NN 4096
#define DQ 128
#define PW 128          // partial/U width: exactly 128 v-cols (den separate)
#define SPLITK 8
#define KCHUNK (NN / SPLITK)   // 512
#define KITERS (KCHUNK / 32)   // 16

// ---------------- scratch (static device globals; no allocation) ----------------
__device__ __half d_E[(size_t)NN * NN];                 // 32 MB: exp(trans) fp16, k-major
__device__ float  d_h[(size_t)NN * DQ];                 // encoder output (layer 0 input)
__device__ __half d_U[(size_t)NN * PW];                 // e^{sa}*v
__device__ __align__(16) __half d_part[(size_t)SPLITK * NN * PW];  // 8.4 MB fp16 split-K partials
__device__ float  d_denp[(size_t)SPLITK * NN];          // fp32 den partials
__device__ float  d_uvec[NN];                           // layer3: e^{sa}*(v . W_dec)
__device__ float  d_evec[NN];                           // per-layer e^{sa} (gemm den; layer3 gemv)
__device__ float  d_gemv_scratch[(size_t)2 * 64 * NN];  // layer3 gemv partials

// ---------------- PTX helpers ----------------
__device__ __forceinline__ uint32_t smem_u32(const void* p) {
    return (uint32_t)__cvta_generic_to_shared(p);
}
__device__ __forceinline__ void ldsm_x4t(uint32_t& r0, uint32_t& r1, uint32_t& r2, uint32_t& r3, uint32_t a) {
    asm volatile("ldmatrix.sync.aligned.m8n8.x4.trans.shared.b16 {%0,%1,%2,%3},[%4];"
                 : "=r"(r0), "=r"(r1), "=r"(r2), "=r"(r3) : "r"(a));
}
__device__ __forceinline__ void mma_f16(float& d0, float& d1, float& d2, float& d3,
                                        uint32_t a0, uint32_t a1, uint32_t a2, uint32_t a3,
                                        uint32_t b0, uint32_t b1) {
    asm volatile(
        "mma.sync.aligned.m16n8k16.row.col.f32.f16.f16.f32 "
        "{%0,%1,%2,%3},{%4,%5,%6,%7},{%8,%9},{%0,%1,%2,%3};"
        : "+f"(d0), "+f"(d1), "+f"(d2), "+f"(d3)
        : "r"(a0), "r"(a1), "r"(a2), "r"(a3), "r"(b0), "r"(b1));
}
__device__ __forceinline__ void cp16(uint32_t dst, const void* src) {
    asm volatile("cp.async.cg.shared.global [%0], [%1], 16;" :: "r"(dst), "l"(src));
}

// ---------------- 1. encode: h = [x|comms] @ W_enc + b_enc ----------------
__global__ __launch_bounds__(128) void encode_kernel(
    const float* __restrict__ x, const float* __restrict__ comms,
    const float* __restrict__ W_enc, const float* __restrict__ b_enc)
{
    const int i0 = blockIdx.x * 16;
    const int c = threadIdx.x;
    __shared__ float in[16][96];
    for (int idx = c; idx < 16 * 64; idx += 128) {
        int r = idx >> 6, t = idx & 63;
        in[r][t] = x[(size_t)(i0 + r) * 64 + t];
    }
    for (int idx = c; idx < 16 * 32; idx += 128) {
        int r = idx >> 5, t = idx & 31;
        in[r][64 + t] = comms[(size_t)(i0 + r) * 32 + t];
    }
    __syncthreads();
    float acc[16];
    const float be = b_enc[c];
#pragma unroll
    for (int r = 0; r < 16; r++) acc[r] = be;
#pragma unroll 4
    for (int t = 0; t < 96; t++) {
        float w = W_enc[t * DQ + c];
#pragma unroll
        for (int r = 0; r < 16; r++) acc[r] += in[r][t] * w;
    }
#pragma unroll
    for (int r = 0; r < 16; r++) d_h[(size_t)(i0 + r) * DQ + c] = acc[r];
}

// ---------------- 2. build E = exp(trans) elementwise ----------------
__global__ __launch_bounds__(256) void buildE_kernel(const float* __restrict__ trans)
{
    const size_t idx = ((size_t)blockIdx.x * 256 + threadIdx.x) * 8;
    float4 v0 = *(const float4*)(trans + idx);
    float4 v1 = *(const float4*)(trans + idx + 4);
    float e[8];
    e[0] = (v0.x == 0.f) ? 0.f : __expf(v0.x);
    e[1] = (v0.y == 0.f) ? 0.f : __expf(v0.y);
    e[2] = (v0.z == 0.f) ? 0.f : __expf(v0.z);
    e[3] = (v0.w == 0.f) ? 0.f : __expf(v0.w);
    e[4] = (v1.x == 0.f) ? 0.f : __expf(v1.x);
    e[5] = (v1.y == 0.f) ? 0.f : __expf(v1.y);
    e[6] = (v1.z == 0.f) ? 0.f : __expf(v1.z);
    e[7] = (v1.w == 0.f) ? 0.f : __expf(v1.w);
    __half2 h2[4];
#pragma unroll
    for (int i = 0; i < 4; i++)
        h2[i] = __floats2half2_rn(e[2 * i], e[2 * i + 1]);
    *(uint4*)(d_E + idx) = *(uint4*)h2;
}

// ---------------- 3. per-layer U; warp-split dual-weight pass (256 thr) ----------------
// grp0 (warps 0-3): W_ad path -> es_s, d_evec. grp1 (warps 4-7): W_av path -> d_U.
__global__ __launch_bounds__(256) void computeU_kernel(
    const float* __restrict__ W_ad, const float* __restrict__ b_ad,
    const float* __restrict__ wa,   const float* __restrict__ W_av,
    const float* __restrict__ b_av, int use_part,
    const float* __restrict__ W_dec)
{
    const int j0 = blockIdx.x * 16;
    const int tid = threadIdx.x;
    const int grp = tid >> 7;         // 0: att/d path, 1: v path
    const int c = tid & 127;
    __shared__ float hr[16][DQ];
    __shared__ float prod[16][DQ + 1];
    __shared__ float es_s[16];
    __shared__ float den[16];
    __shared__ float vdot[16];

    if (!use_part) {
#pragma unroll
        for (int r8 = 0; r8 < 8; r8++) {
            int r = grp * 8 + r8;
            hr[r][c] = d_h[(size_t)(j0 + r) * DQ + c];
        }
        __syncthreads();
    } else {
        if (grp == 0 && c < 16) {
            float d = 0.f;
#pragma unroll
            for (int s = 0; s < SPLITK; s++)
                d += d_denp[(size_t)s * NN + j0 + c];
            den[c] = d;
        }
#pragma unroll
        for (int r8 = 0; r8 < 8; r8++) {
            int r = grp * 8 + r8;
            float num = 0.f;
#pragma unroll
            for (int s = 0; s < SPLITK; s++)
                num += __half2float(d_part[((size_t)s * NN + j0 + r) * PW + c]);
            hr[r][c] = num;
        }
        __syncthreads();
#pragma unroll
        for (int r8 = 0; r8 < 8; r8++) {
            int r = grp * 8 + r8;
            hr[r][c] = hr[r][c] / den[r];
        }
        __syncthreads();
    }

    const float* W = grp ? W_av : W_ad;
    const float bb = grp ? b_av[c] : b_ad[c];
    float acc[16];
#pragma unroll
    for (int r = 0; r < 16; r++) acc[r] = bb;
#pragma unroll 4
    for (int t = 0; t < DQ; t++) {
        float w = W[t * DQ + c];
#pragma unroll
        for (int r = 0; r < 16; r++) acc[r] += hr[r][t] * w;
    }

    if (grp == 0) {
        const float wac = wa[c];
#pragma unroll
        for (int r = 0; r < 16; r++) prod[r][c] = acc[r] * wac;
    }
    __syncthreads();

    const int warp = tid >> 5, lane = tid & 31;
    if (grp == 0) {
#pragma unroll
        for (int rr = 0; rr < 4; rr++) {
            int r = warp * 4 + rr;
            float s = prod[r][lane] + prod[r][lane + 32] + prod[r][lane + 64] + prod[r][lane + 96];
#pragma unroll
            for (int o = 16; o > 0; o >>= 1) s += __shfl_xor_sync(0xffffffff, s, o);
            if (lane == 0) es_s[r] = __expf(s);
        }
    }
    __syncthreads();

    if (W_dec == nullptr) {
        if (grp == 1) {
#pragma unroll
            for (int r = 0; r < 16; r++)
                d_U[(size_t)(j0 + r) * PW + c] = __float2half(es_s[r] * acc[r]);
        } else if (c < 16) {
            d_evec[j0 + c] = es_s[c];
        }
    } else {
        if (grp == 1) {
            const float wdc = W_dec[c];
#pragma unroll
            for (int r = 0; r < 16; r++) prod[r][c] = acc[r] * wdc;
        }
        __syncthreads();
        if (grp == 1) {
#pragma unroll
            for (int rr = 0; rr < 4; rr++) {
                int r = (warp - 4) * 4 + rr;
                float s = prod[r][lane] + prod[r][lane + 32] + prod[r][lane + 64] + prod[r][lane + 96];
#pragma unroll
                for (int o = 16; o > 0; o >>= 1) s += __shfl_xor_sync(0xffffffff, s, o);
                if (lane == 0) vdot[r] = s;
            }
        }
        __syncthreads();
        if (grp == 0 && c < 16) {
            d_uvec[j0 + c] = es_s[c] * vdot[c];
            d_evec[j0 + c] = es_s[c];
        }
    }
}

// ---------------- 4. split-K fp16 GEMM: BM=128, BN=128, fused den (half2) ----------------
// part[s][i][n] = sum_{j in chunk s} E[j][i]*U[j][n];  denp[s][i] = sum_j E[j][i]*e[j]
// SPLITK=8 -> grid 256 = ONE full wave at 2 CTA/SM. 4-buffer / 3-deep cp.async.
#define AST 136                            // 128 + 8 pad halfs
#define ABUF 4352                          // 32*136 halfs per buffer
#define SE_OFF (8 * ABUF)                  // floats after 8 half-buffers
#define GEMM_SMEM (8 * ABUF * 2 + (128 + 512) * 4)

__global__ __launch_bounds__(256, 2) void gemm_kernel()
{
    extern __shared__ __half sm[];
    float* se = (float*)(sm + SE_OFF);          // [4][32]
    float* sden = se + 128;                     // [4][128]

    const int tid = threadIdx.x;
    const int m0 = blockIdx.x * 128;
    const size_t ks = (size_t)blockIdx.y * KCHUNK;
    const int warp = tid >> 5, lane = tid & 31;
    const int wm = (warp & 3) * 32, wn = (warp >> 2) * 64;

    float acc[2][8][4];
#pragma unroll
    for (int mi = 0; mi < 2; mi++)
#pragma unroll
        for (int i = 0; i < 8; i++)
            acc[mi][i][0] = acc[mi][i][1] = acc[mi][i][2] = acc[mi][i][3] = 0.f;
    float den0 = 0.f, den1 = 0.f;

    // cp.async: each tile 32 rows x 128 halfs = 512 16B-chunks, 2/thread
    const int r0 = tid >> 4, cc0 = (tid & 15) * 8;
    const int r1 = 16 + r0;
    const __half* Eg = d_E + ks * NN + m0;   // E[k][m]
    const __half* Ug = d_U + ks * PW;        // U[k][n]
    const float* ev = d_evec + ks;

#define ISSUE_STAGE(buf, kb)                                                      \
    do {                                                                          \
        const __half* Ea = Eg + (size_t)(kb) * NN;                                \
        const __half* Ua = Ug + (size_t)(kb) * PW;                                \
        cp16(smem_u32(&sm[(buf) * ABUF + r0 * AST + cc0]), Ea + (size_t)r0 * NN + cc0); \
        cp16(smem_u32(&sm[(buf) * ABUF + r1 * AST + cc0]), Ea + (size_t)r1 * NN + cc0); \
        cp16(smem_u32(&sm[(4 + (buf)) * ABUF + r0 * AST + cc0]), Ua + (size_t)r0 * PW + cc0); \
        cp16(smem_u32(&sm[(4 + (buf)) * ABUF + r1 * AST + cc0]), Ua + (size_t)r1 * PW + cc0); \
        if (tid >= 224) se[(buf) * 32 + tid - 224] = ev[(kb) + tid - 224];        \
        asm volatile("cp.async.commit_group;");                                   \
    } while (0)

    ISSUE_STAGE(0, 0);
    ISSUE_STAGE(1, 32);
    ISSUE_STAGE(2, 64);

    // den layout: thread owns m-pair m2 = (tid&63)*2, k-range kh = (tid>>6)*8 (8 k's)
    const int m2 = (tid & 63) * 2, kh = (tid >> 6) * 8;

#pragma unroll 1
    for (int it = 0; it < KITERS; it++) {
        const int buf = it & 3;
        if (it < KITERS - 2)       asm volatile("cp.async.wait_group 2;" ::: "memory");
        else if (it == KITERS - 2) asm volatile("cp.async.wait_group 1;" ::: "memory");
        else                       asm volatile("cp.async.wait_group 0;" ::: "memory");
        __syncthreads();

        // issue stage it+3 into buf (it+3)&3 — its previous contents were consumed at
        // iter it-1; the barrier above proves all warps are past that consumption.
        if (it + 3 < KITERS) ISSUE_STAGE((it + 3) & 3, (it + 3) * 32);

        // fused den (half2): den[m2,m2+1] += sum_k E[k][m2..m2+1]*e[k]
#pragma unroll
        for (int k2 = 0; k2 < 8; k2++) {
            const float2 ef = __half22float2(
                *(const __half2*)&sm[buf * ABUF + (kh + k2) * AST + m2]);
            const float w = se[buf * 32 + kh + k2];
            den0 += ef.x * w;
            den1 += ef.y * w;
        }

#pragma unroll
        for (int kk = 0; kk < 2; kk++) {
            const int arow = kk * 16 + (lane & 7) + ((lane >> 4) << 3);
            const int acb = wm + ((lane >> 3) & 1) * 8;
            uint32_t a0[4], a1[4];
            ldsm_x4t(a0[0], a0[1], a0[2], a0[3],
                     smem_u32(&sm[buf * ABUF + arow * AST + acb]));
            ldsm_x4t(a1[0], a1[1], a1[2], a1[3],
                     smem_u32(&sm[buf * ABUF + arow * AST + acb + 16]));
#pragma unroll
            for (int nf = 0; nf < 4; nf++) {
                uint32_t b0, b1, b2, b3;
                ldsm_x4t(b0, b1, b2, b3,
                         smem_u32(&sm[(4 + buf) * ABUF + (kk * 16 + (lane & 15)) * AST
                                      + wn + nf * 16 + (lane >> 4) * 8]));
                float* c00 = acc[0][2 * nf];
                float* c01 = acc[0][2 * nf + 1];
                float* c10 = acc[1][2 * nf];
                float* c11 = acc[1][2 * nf + 1];
                mma_f16(c00[0], c00[1], c00[2], c00[3], a0[0], a0[1], a0[2], a0[3], b0, b1);
                mma_f16(c01[0], c01[1], c01[2], c01[3], a0[0], a0[1], a0[2], a0[3], b2, b3);
                mma_f16(c10[0], c10[1], c10[2], c10[3], a1[0], a1[1], a1[2], a1[3], b0, b1);
                mma_f16(c11[0], c11[1], c11[2], c11[3], a1[0], a1[1], a1[2], a1[3], b2, b3);
            }
        }
    }

    // epilogue: fp16 split partials + fp32 den partial
    const int g = lane >> 2, tg = lane & 3;
    __half* P = d_part + ((size_t)blockIdx.y * NN + m0 + wm) * PW + wn;
#pragma unroll
    for (int mi = 0; mi < 2; mi++) {
#pragma unroll
        for (int fi = 0; fi < 8; fi++) {
            int col = fi * 8 + tg * 2;
            int rr0 = mi * 16 + g;
            *(__half2*)&P[(size_t)rr0 * PW + col] =
                __floats2half2_rn(acc[mi][fi][0], acc[mi][fi][1]);
            *(__half2*)&P[(size_t)(rr0 + 8) * PW + col] =
                __floats2half2_rn(acc[mi][fi][2], acc[mi][fi][3]);
        }
    }
    sden[(tid >> 6) * 128 + m2] = den0;
    sden[(tid >> 6) * 128 + m2 + 1] = den1;
    __syncthreads();
    if (tid < 128)
        d_denp[(size_t)blockIdx.y * NN + m0 + tid] =
            sden[tid] + sden[128 + tid] + sden[256 + tid] + sden[384 + tid];
#undef ISSUE_STAGE
}

// ---------------- 5. layer-3 GEMV: colsum of E weighted by u / e ----------------
#define JCH 64
#define NJC (NN / JCH)  // 64 chunks
__global__ __launch_bounds__(256) void gemv_kernel()
{
    float* gnum = d_gemv_scratch;                // [NJC][NN]
    float* gden = gnum + (size_t)NJC * NN;
    const int i0 = blockIdx.x * 1024;
    const int j0 = blockIdx.y * JCH;
    const int t = threadIdx.x;
    __shared__ float su[JCH], sev[JCH];
    if (t < JCH) { su[t] = d_uvec[j0 + t]; sev[t] = d_evec[j0 + t]; }
    __syncthreads();

    float n0 = 0.f, n1 = 0.f, n2 = 0.f, n3 = 0.f;
    float e0 = 0.f, e1 = 0.f, e2 = 0.f, e3 = 0.f;
    const __half* Eb = d_E + (size_t)j0 * NN + i0 + 2 * t;
#pragma unroll 4
    for (int j = 0; j < JCH; j++) {
        const float u = su[j], evv = sev[j];
        const __half2 a = *(const __half2*)(Eb + (size_t)j * NN);
        const __half2 b = *(const __half2*)(Eb + (size_t)j * NN + 512);
        const float2 af = __half22float2(a);
        const float2 bf = __half22float2(b);
        n0 += af.x * u;   n1 += af.y * u;
        n2 += bf.x * u;   n3 += bf.y * u;
        e0 += af.x * evv; e1 += af.y * evv;
        e2 += bf.x * evv; e3 += bf.y * evv;
    }
    const size_t base = (size_t)blockIdx.y * NN + i0 + 2 * t;
    *(float2*)&gnum[base] = make_float2(n0, n1);
    *(float2*)&gnum[base + 512] = make_float2(n2, n3);
    *(float2*)&gden[base] = make_float2(e0, e1);
    *(float2*)&gden[base + 512] = make_float2(e2, e3);
}

// ---------------- 6. finalize: out = num/den + b_dec (+mask) ----------------
__global__ __launch_bounds__(128) void finalize_kernel(
    const float* __restrict__ b_dec, const int* __restrict__ mask,
    float* __restrict__ out)
{
    const float* gnum = d_gemv_scratch;
    const float* gden = gnum + (size_t)NJC * NN;
    const int i = blockIdx.x * 128 + threadIdx.x;
    float num = 0.f, den = 0.f;
#pragma unroll 8
    for (int jc = 0; jc < NJC; jc++) {
        num += gnum[(size_t)jc * NN + i];
        den += gden[(size_t)jc * NN + i];
    }
    out[i] = (mask[i] == 0) ? __int_as_float(0xff800000)
                            : (num / den + b_dec[0]);
}

// ---------------- launch ----------------
extern "C" void kernel_launch(void* const* d_in, const int* in_sizes, int n_in,
                              void* d_out, int out_size)
{
    const float* x      = (const float*)d_in[0];
    const float* comms  = (const float*)d_in[1];
    const float* trans  = (const float*)d_in[2];
    const int*   mask   = (const int*)d_in[3];
    const float* W_enc  = (const float*)d_in[4];
    const float* b_enc  = (const float*)d_in[5];
    const float* W_ad   = (const float*)d_in[6];
    const float* b_ad   = (const float*)d_in[7];
    const float* w_att  = (const float*)d_in[8];
    // d_in[9] = b_att: cancels in row-softmax, unused
    const float* W_av   = (const float*)d_in[10];
    const float* b_av   = (const float*)d_in[11];
    const float* W_dec  = (const float*)d_in[12];
    const float* b_dec  = (const float*)d_in[13];
    float* out = (float*)d_out;

    cudaFuncSetAttribute(gemm_kernel, cudaFuncAttributeMaxDynamicSharedMemorySize,
                         GEMM_SMEM);

    encode_kernel<<<NN / 16, 128>>>(x, comms, W_enc, b_enc);
    buildE_kernel<<<(NN * (size_t)NN) / (256 * 8), 256>>>(trans);

    for (int k = 0; k < 3; k++) {
        computeU_kernel<<<NN / 16, 256>>>(W_ad + (size_t)k * DQ * DQ,
                                          b_ad + (size_t)k * DQ,
                                          w_att + (size_t)k * 2 * DQ,   // wa = first half
                                          W_av + (size_t)k * DQ * DQ,
                                          b_av + (size_t)k * DQ,
                                          k > 0,
                                          (k == 2) ? W_dec : nullptr);
        if (k < 2)
            gemm_kernel<<<dim3(NN / 128, SPLITK), 256, GEMM_SMEM>>>();
    }
    gemv_kernel<<<dim3(4, NJC), 256>>>();
    finalize_kernel<<<NN / 128, 128>>>(b_dec, mask, out);
}